// round 2
// baseline (speedup 1.0000x reference)
#include <cuda_runtime.h>
#include <cuda_bf16.h>
#include <cstdint>

// ---------------- problem constants (fixed shapes) ----------------
#define NN     131072      // nodes
#define EE     2097152     // edges
#define GG     8192        // graphs
#define NPG    16
#define NSLOT  16384       // 2 per graph
#define DIMX   128
#define GS     64
#define NOUT   200
#define KS     8           // K-split for decode
#define ELIST_CAP 524288

// ---------------- scratch (device globals; no runtime alloc) ----------------
__device__ int   d_mark[NN];
__device__ int   d_node_of[NSLOT];
__device__ int   d_cnt[NSLOT];
__device__ int   d_off[NSLOT + 1];
__device__ int   d_cur[NSLOT];
__device__ int   d_elist[ELIST_CAP];
__device__ float d_MX[NSLOT * 256];        // [slot][mean(128) | xv(128)]
__device__ float d_H[NSLOT * GS];          // h per slot
__device__ float d_S[GG * 128];            // fused ir features
__device__ float d_Zp[(size_t)KS * GG * 208]; // decode partials

// ---------------- stage A: mark / count / scan / fill / aggregate ----------------
__global__ void k_mark(const int* __restrict__ set_idx) {
    int s = blockIdx.x * blockDim.x + threadIdx.x;
    if (s >= NSLOT) return;
    int g = s >> 1, k = s & 1;
    int v = g * NPG + set_idx[g * 2 + k];
    d_node_of[s] = v;
    atomicMax(&d_mark[v], s);
}

__global__ void k_count(const int* __restrict__ ei) {
    int e = blockIdx.x * blockDim.x + threadIdx.x;
    if (e >= EE) return;
    int dst = ei[EE + e];
    int r = d_mark[dst];
    if (r >= 0) atomicAdd(&d_cnt[r], 1);
}

__global__ void k_scan() {
    __shared__ int ssum[1024];
    int t = threadIdx.x;
    int local[16]; int s = 0;
#pragma unroll
    for (int j = 0; j < 16; j++) { local[j] = d_cnt[t * 16 + j]; s += local[j]; }
    ssum[t] = s; __syncthreads();
    for (int d = 1; d < 1024; d <<= 1) {
        int v = (t >= d) ? ssum[t - d] : 0;
        __syncthreads();
        ssum[t] += v;
        __syncthreads();
    }
    int base = (t == 0) ? 0 : ssum[t - 1];
#pragma unroll
    for (int j = 0; j < 16; j++) { d_off[t * 16 + j] = base; base += local[j]; }
    if (t == 1023) d_off[NSLOT] = base;
}

__global__ void k_fill(const int* __restrict__ ei) {
    int e = blockIdx.x * blockDim.x + threadIdx.x;
    if (e >= EE) return;
    int dst = ei[EE + e];
    int r = d_mark[dst];
    if (r >= 0) {
        int pos = atomicAdd(&d_cur[r], 1);
        int q = d_off[r] + pos;
        if (q < ELIST_CAP) d_elist[q] = ei[e];
    }
}

__global__ void k_agg(const float* __restrict__ x) {
    int s = blockIdx.x * 8 + (threadIdx.x >> 5);
    int lane = threadIdx.x & 31;
    int v = d_node_of[s];
    if (d_mark[v] != s) return;                  // duplicate; filled by k_fix
    const float4* x4 = (const float4*)x;
    int beg = d_off[s], end = d_off[s + 1];
    float4 acc = make_float4(0.f, 0.f, 0.f, 0.f);
    for (int idx = beg; idx < end; idx++) {
        int src = d_elist[idx];
        float4 t = x4[(size_t)src * 32 + lane];
        acc.x += t.x; acc.y += t.y; acc.z += t.z; acc.w += t.w;
    }
    int deg = end - beg;
    float inv = 1.f / (float)(deg > 0 ? deg : 1);
    acc.x *= inv; acc.y *= inv; acc.z *= inv; acc.w *= inv;
    float4* MX4 = (float4*)d_MX;
    MX4[(size_t)s * 64 + lane]      = acc;
    MX4[(size_t)s * 64 + 32 + lane] = x4[(size_t)v * 32 + lane];
}

__global__ void k_fix() {
    int s = blockIdx.x * 8 + (threadIdx.x >> 5);
    int lane = threadIdx.x & 31;
    int v = d_node_of[s];
    int rep = d_mark[v];
    if (rep == s) return;
    float4* MX4 = (float4*)d_MX;
    MX4[(size_t)s * 64 + lane]      = MX4[(size_t)rep * 64 + lane];
    MX4[(size_t)s * 64 + 32 + lane] = MX4[(size_t)rep * 64 + 32 + lane];
}

// ---------------- stage B: H = relu(MX @ [Wl;Wr] + bl)  (fp32 SGEMM) ----------------
__global__ void k_hgemm(const float* __restrict__ Wl, const float* __restrict__ Wr,
                        const float* __restrict__ bl) {
    __shared__ float As[16][132];   // [k][row], transposed
    __shared__ float Bs[16][64];
    int tid = threadIdx.x;
    int tx = tid & 15, ty = tid >> 4;
    int row0 = blockIdx.x * 128;
    float acc[8][4];
#pragma unroll
    for (int i = 0; i < 8; i++)
#pragma unroll
        for (int j = 0; j < 4; j++) acc[i][j] = 0.f;

    for (int kb = 0; kb < 256; kb += 16) {
        for (int l = tid; l < 512; l += 256) {
            int r = l >> 2, q = l & 3;
            float4 v = *(const float4*)&d_MX[(size_t)(row0 + r) * 256 + kb + q * 4];
            As[q * 4 + 0][r] = v.x; As[q * 4 + 1][r] = v.y;
            As[q * 4 + 2][r] = v.z; As[q * 4 + 3][r] = v.w;
        }
        {
            int k = tid >> 4, o4 = (tid & 15) * 4;
            int kg = kb + k;
            const float* Wsrc = (kg < 128) ? &Wl[kg * 64 + o4] : &Wr[(kg - 128) * 64 + o4];
            *(float4*)&Bs[k][o4] = *(const float4*)Wsrc;
        }
        __syncthreads();
#pragma unroll
        for (int k = 0; k < 16; k++) {
            float a[8], b[4];
#pragma unroll
            for (int i = 0; i < 8; i++) a[i] = As[k][ty * 8 + i];
#pragma unroll
            for (int j = 0; j < 4; j++) b[j] = Bs[k][tx * 4 + j];
#pragma unroll
            for (int i = 0; i < 8; i++)
#pragma unroll
                for (int j = 0; j < 4; j++) acc[i][j] += a[i] * b[j];
        }
        __syncthreads();
    }
#pragma unroll
    for (int i = 0; i < 8; i++)
#pragma unroll
        for (int j = 0; j < 4; j++) {
            int o = tx * 4 + j;
            d_H[(size_t)(row0 + ty * 8 + i) * 64 + o] = fmaxf(acc[i][j] + bl[o], 0.f);
        }
}

// ---------------- stage C: S = relu(ir @ Wir + bir) ----------------
__global__ void k_sgemm(const float* __restrict__ ir, const float* __restrict__ Wir,
                        const float* __restrict__ bir) {
    __shared__ float irs[64][32];
    __shared__ float Ws[32][128];
    int tid = threadIdx.x;
    int g0 = blockIdx.x * 64;
    for (int l = tid; l < 64 * 32; l += 256) irs[l >> 5][l & 31] = ir[(size_t)g0 * 32 + l];
    for (int l = tid; l < 32 * 128; l += 256) Ws[l >> 7][l & 127] = Wir[l];
    __syncthreads();
    int o = tid & 127, h = tid >> 7;
    float bo = bir[o];
    for (int gg = h; gg < 64; gg += 2) {
        float acc = bo;
#pragma unroll
        for (int k = 0; k < 32; k++) acc += irs[gg][k] * Ws[k][o];
        d_S[(size_t)(g0 + gg) * 128 + o] = fmaxf(acc, 0.f);
    }
}

// ---------------- stage D: decode GEMM  Zp[z] = A_z @ W1_z  (tf32 HMMA) ----------------
#define SS_STRIDE 132
#define BS_STRIDE 216
#define NSTAGE 3
#define SMEM_FLOATS (128 * SS_STRIDE + 16 * 128 + NSTAGE * 16 * BS_STRIDE)

__device__ __forceinline__ unsigned su32(const void* p) {
    return (unsigned)__cvta_generic_to_shared(p);
}

__global__ void __launch_bounds__(256, 1)
k_decode(const float* __restrict__ W1) {
    extern __shared__ float sm[];
    float* Ss = sm;                                 // [128][132]
    float* Ps = Ss + 128 * SS_STRIDE;               // [16][128]
    float* Bs = Ps + 16 * 128;                      // [NSTAGE][16][216]

    int tid = threadIdx.x;
    int lane = tid & 31, warp = tid >> 5;
    int wm = warp >> 1, wn = warp & 1;
    int gq = lane >> 2, l4 = lane & 3;
    int mb = blockIdx.x, z = blockIdx.y;
    int g0 = mb * 128;

    // S tile (fp32; HW truncates to tf32 inside HMMA)
    for (int l = tid; l < 128 * 128; l += 256) {
        int r = l >> 7, j = l & 127;
        Ss[r * SS_STRIDE + j] = d_S[(size_t)(g0 + r) * 128 + j];
    }
    // P tile: P[g][i] = H[2g + (i>=64)][i&63], i in [16z, 16z+16)
    for (int l = tid; l < 16 * 128; l += 256) {
        int il = l >> 7, r = l & 127;
        int i = z * 16 + il;
        int s = 2 * (g0 + r) + (i >= 64 ? 1 : 0);
        Ps[il * 128 + r] = d_H[(size_t)s * 64 + (i & 63)];
    }

    // B stage loader: 16 K-rows x 208 cols (200 real + 8 zero-filled)
    auto load_stage = [&](int buf, int sidx) {
        int kb = z * 2048 + sidx * 16;
        for (int l = tid; l < 16 * 52; l += 256) {
            int row = l / 52, c = l % 52;
            unsigned dst = su32(&Bs[(buf * 16 + row) * BS_STRIDE + c * 4]);
            const float* src = (c < 50) ? (W1 + (size_t)(kb + row) * 200 + c * 4) : W1;
            int sz = (c < 50) ? 16 : 0;
            asm volatile("cp.async.cg.shared.global [%0], [%1], 16, %2;\n"
                         :: "r"(dst), "l"(src), "r"(sz));
        }
        asm volatile("cp.async.commit_group;\n");
    };

    load_stage(0, 0);
    load_stage(1, 1);

    float acc[2][13][4];
#pragma unroll
    for (int a = 0; a < 2; a++)
#pragma unroll
        for (int b = 0; b < 13; b++)
#pragma unroll
            for (int c = 0; c < 4; c++) acc[a][b][c] = 0.f;

    float p[2][2];
    int cur_i = -1;

    for (int s_ = 0; s_ < 128; s_++) {
        asm volatile("cp.async.wait_group %0;\n" :: "n"(NSTAGE - 2));
        __syncthreads();

        int nxt = s_ + 2;
        if (nxt < 128) load_stage(nxt % NSTAGE, nxt);
        else asm volatile("cp.async.commit_group;\n");

        int ib = s_ >> 3;
        if (ib != cur_i) {
            cur_i = ib;
#pragma unroll
            for (int mt = 0; mt < 2; mt++) {
                int r0 = wm * 32 + mt * 16 + gq;
                p[mt][0] = Ps[ib * 128 + r0];
                p[mt][1] = Ps[ib * 128 + r0 + 8];
            }
        }
        const float* Bst = Bs + (s_ % NSTAGE) * 16 * BS_STRIDE;
        int jb = (s_ & 7) * 16;
#pragma unroll
        for (int kk = 0; kk < 16; kk += 8) {
            int j = jb + kk + l4;
            unsigned a[2][4];
#pragma unroll
            for (int mt = 0; mt < 2; mt++) {
                int r0 = wm * 32 + mt * 16 + gq, r1 = r0 + 8;
                float s00 = Ss[r0 * SS_STRIDE + j];
                float s10 = Ss[r1 * SS_STRIDE + j];
                float s01 = Ss[r0 * SS_STRIDE + j + 4];
                float s11 = Ss[r1 * SS_STRIDE + j + 4];
                a[mt][0] = __float_as_uint(p[mt][0] * s00);
                a[mt][1] = __float_as_uint(p[mt][1] * s10);
                a[mt][2] = __float_as_uint(p[mt][0] * s01);
                a[mt][3] = __float_as_uint(p[mt][1] * s11);
            }
#pragma unroll
            for (int n8 = 0; n8 < 13; n8++) {
                int col = wn * 104 + n8 * 8 + gq;
                unsigned b0 = __float_as_uint(Bst[(kk + l4) * BS_STRIDE + col]);
                unsigned b1 = __float_as_uint(Bst[(kk + l4 + 4) * BS_STRIDE + col]);
#pragma unroll
                for (int mt = 0; mt < 2; mt++) {
                    asm volatile(
                        "mma.sync.aligned.m16n8k8.row.col.f32.tf32.tf32.f32 "
                        "{%0,%1,%2,%3}, {%4,%5,%6,%7}, {%8,%9}, {%0,%1,%2,%3};"
                        : "+f"(acc[mt][n8][0]), "+f"(acc[mt][n8][1]),
                          "+f"(acc[mt][n8][2]), "+f"(acc[mt][n8][3])
                        : "r"(a[mt][0]), "r"(a[mt][1]), "r"(a[mt][2]), "r"(a[mt][3]),
                          "r"(b0), "r"(b1));
                }
            }
        }
    }

    // store partial tile
#pragma unroll
    for (int mt = 0; mt < 2; mt++) {
        int gr = g0 + wm * 32 + mt * 16 + gq;
#pragma unroll
        for (int n8 = 0; n8 < 13; n8++) {
            int c0 = wn * 104 + n8 * 8 + 2 * l4;
            if (c0 < NOUT) {
                size_t b0 = ((size_t)z * GG + gr) * 208;
                size_t b1 = ((size_t)z * GG + gr + 8) * 208;
                *(float2*)&d_Zp[b0 + c0] = make_float2(acc[mt][n8][0], acc[mt][n8][1]);
                *(float2*)&d_Zp[b1 + c0] = make_float2(acc[mt][n8][2], acc[mt][n8][3]);
            }
        }
    }
}

// ---------------- epilogue: sum partials, bias+relu, @W2 ----------------
__global__ void k_final(const float* __restrict__ b1, const float* __restrict__ W2,
                        const float* __restrict__ b2, float* __restrict__ out) {
    int g = (blockIdx.x * blockDim.x + threadIdx.x) >> 5;
    int lane = threadIdx.x & 31;
    if (g >= GG) return;
    float a0 = 0.f, a1 = 0.f;
    for (int n = lane; n < NOUT; n += 32) {
        float v = b1[n];
#pragma unroll
        for (int zz = 0; zz < KS; zz++) v += d_Zp[((size_t)zz * GG + g) * 208 + n];
        v = fmaxf(v, 0.f);
        a0 += v * W2[n * 2];
        a1 += v * W2[n * 2 + 1];
    }
#pragma unroll
    for (int o = 16; o; o >>= 1) {
        a0 += __shfl_down_sync(0xffffffffu, a0, o);
        a1 += __shfl_down_sync(0xffffffffu, a1, o);
    }
    if (lane == 0) { out[g * 2] = a0 + b2[0]; out[g * 2 + 1] = a1 + b2[1]; }
}

// ---------------- host ----------------
extern "C" void kernel_launch(void* const* d_in, const int* in_sizes, int n_in,
                              void* d_out, int out_size) {
    const float* x       = (const float*)d_in[0];
    const int*   ei      = (const int*)d_in[1];
    const int*   set_idx = (const int*)d_in[2];
    const float* ir      = (const float*)d_in[4];
    const float* Wl      = (const float*)d_in[5];
    const float* bl      = (const float*)d_in[6];
    const float* Wr      = (const float*)d_in[7];
    const float* Wir     = (const float*)d_in[8];
    const float* bir     = (const float*)d_in[9];
    const float* W1      = (const float*)d_in[10];
    const float* b1      = (const float*)d_in[11];
    const float* W2      = (const float*)d_in[12];
    const float* b2      = (const float*)d_in[13];
    float* out = (float*)d_out;

    void *p_mark, *p_cnt, *p_cur;
    cudaGetSymbolAddress(&p_mark, d_mark);
    cudaGetSymbolAddress(&p_cnt,  d_cnt);
    cudaGetSymbolAddress(&p_cur,  d_cur);
    cudaMemsetAsync(p_mark, 0xFF, (size_t)NN * 4, 0);
    cudaMemsetAsync(p_cnt,  0,    (size_t)NSLOT * 4, 0);
    cudaMemsetAsync(p_cur,  0,    (size_t)NSLOT * 4, 0);

    k_mark<<<NSLOT / 256, 256>>>(set_idx);
    k_count<<<EE / 256, 256>>>(ei);
    k_scan<<<1, 1024>>>();
    k_fill<<<EE / 256, 256>>>(ei);
    k_agg<<<NSLOT / 8, 256>>>(x);
    k_fix<<<NSLOT / 8, 256>>>();
    k_hgemm<<<NSLOT / 128, 256>>>(Wl, Wr, bl);
    k_sgemm<<<GG / 64, 256>>>(ir, Wir, bir);

    static int smem_set = 0;
    size_t smem_bytes = (size_t)SMEM_FLOATS * 4;
    cudaFuncSetAttribute(k_decode, cudaFuncAttributeMaxDynamicSharedMemorySize,
                         (int)smem_bytes);
    (void)smem_set;
    k_decode<<<dim3(GG / 128, KS), 256, smem_bytes>>>(W1);

    k_final<<<(GG * 32 + 255) / 256, 256>>>(b1, W2, b2, out);
}

// round 6
// speedup vs baseline: 1.6908x; 1.6908x over previous
#include <cuda_runtime.h>
#include <cuda_fp16.h>
#include <cstdint>

// ---------------- problem constants (fixed shapes) ----------------
#define NN     131072      // nodes
#define EE     2097152     // edges
#define GG     8192        // graphs
#define NPG    16
#define NSLOT  16384       // 2 per graph
#define GS     64
#define NOUT   200
#define KS     2           // K-split for decode
#define ELIST_CAP 524288

// ---------------- scratch (device globals; no runtime alloc) ----------------
__device__ int    d_mark[NN];
__device__ int    d_node_of[NSLOT];
__device__ int    d_cnt[NSLOT];
__device__ int    d_off[NSLOT + 1];
__device__ int    d_cur[NSLOT];
__device__ int    d_elist[ELIST_CAP];
__device__ float  d_MX[NSLOT * 256];          // [slot][mean(128) | xv(128)]
__device__ __half d_Hh[NSLOT * GS];           // h per slot (fp16)
__device__ __half d_Sh[GG * 128];             // fused ir features (fp16)
__device__ __half d_W1h[208 * 16384];         // W1 transposed (n-major), fp16, zero-padded
__device__ float  d_Zp[(size_t)KS * GG * 208];// decode partials

__device__ __forceinline__ uint32_t su32(const void* p) {
    return (uint32_t)__cvta_generic_to_shared(p);
}

// ---------------- stage 0: W1 transpose + fp16 round ----------------
__global__ void k_prep(const float* __restrict__ W1) {
    __shared__ float tile[32][33];
    int kb = blockIdx.x * 32, nb = blockIdx.y * 32;
    int tx = threadIdx.x, ty = threadIdx.y;
#pragma unroll
    for (int r = 0; r < 4; r++) {
        int k = kb + ty + r * 8;
        int n = nb + tx;
        tile[ty + r * 8][tx] = (n < NOUT) ? W1[(size_t)k * NOUT + n] : 0.f;
    }
    __syncthreads();
#pragma unroll
    for (int r = 0; r < 4; r++) {
        int n = nb + ty + r * 8;
        if (n < 208) d_W1h[(size_t)n * 16384 + kb + tx] = __float2half_rn(tile[tx][ty + r * 8]);
    }
}

// ---------------- stage A: mark / count / scan / fill / aggregate ----------------
__global__ void k_mark(const int* __restrict__ set_idx) {
    int s = blockIdx.x * blockDim.x + threadIdx.x;
    if (s >= NSLOT) return;
    int g = s >> 1, k = s & 1;
    int v = g * NPG + set_idx[g * 2 + k];
    d_node_of[s] = v;
    atomicMax(&d_mark[v], s);
}

__global__ void k_count(const int* __restrict__ ei) {
    int e = blockIdx.x * blockDim.x + threadIdx.x;
    if (e >= EE) return;
    int dst = ei[EE + e];
    int r = d_mark[dst];
    if (r >= 0) atomicAdd(&d_cnt[r], 1);
}

__global__ void k_scan() {
    __shared__ int ssum[1024];
    int t = threadIdx.x;
    int local[16]; int s = 0;
#pragma unroll
    for (int j = 0; j < 16; j++) { local[j] = d_cnt[t * 16 + j]; s += local[j]; }
    ssum[t] = s; __syncthreads();
    for (int d = 1; d < 1024; d <<= 1) {
        int v = (t >= d) ? ssum[t - d] : 0;
        __syncthreads();
        ssum[t] += v;
        __syncthreads();
    }
    int base = (t == 0) ? 0 : ssum[t - 1];
#pragma unroll
    for (int j = 0; j < 16; j++) { d_off[t * 16 + j] = base; base += local[j]; }
    if (t == 1023) d_off[NSLOT] = base;
}

__global__ void k_fill(const int* __restrict__ ei) {
    int e = blockIdx.x * blockDim.x + threadIdx.x;
    if (e >= EE) return;
    int dst = ei[EE + e];
    int r = d_mark[dst];
    if (r >= 0) {
        int pos = atomicAdd(&d_cur[r], 1);
        int q = d_off[r] + pos;
        if (q < ELIST_CAP) d_elist[q] = ei[e];
    }
}

__global__ void k_agg(const float* __restrict__ x) {
    int s = blockIdx.x * 8 + (threadIdx.x >> 5);
    int lane = threadIdx.x & 31;
    int v = d_node_of[s];
    if (d_mark[v] != s) return;                  // duplicate; filled by k_fix
    const float4* x4 = (const float4*)x;
    int beg = d_off[s], end = d_off[s + 1];
    float4 acc = make_float4(0.f, 0.f, 0.f, 0.f);
    for (int idx = beg; idx < end; idx++) {
        int src = d_elist[idx];
        float4 t = x4[(size_t)src * 32 + lane];
        acc.x += t.x; acc.y += t.y; acc.z += t.z; acc.w += t.w;
    }
    int deg = end - beg;
    float inv = 1.f / (float)(deg > 0 ? deg : 1);
    acc.x *= inv; acc.y *= inv; acc.z *= inv; acc.w *= inv;
    float4* MX4 = (float4*)d_MX;
    MX4[(size_t)s * 64 + lane]      = acc;
    MX4[(size_t)s * 64 + 32 + lane] = x4[(size_t)v * 32 + lane];
}

__global__ void k_fix() {
    int s = blockIdx.x * 8 + (threadIdx.x >> 5);
    int lane = threadIdx.x & 31;
    int v = d_node_of[s];
    int rep = d_mark[v];
    if (rep == s) return;
    float4* MX4 = (float4*)d_MX;
    MX4[(size_t)s * 64 + lane]      = MX4[(size_t)rep * 64 + lane];
    MX4[(size_t)s * 64 + 32 + lane] = MX4[(size_t)rep * 64 + 32 + lane];
}

// ---------------- stage B: H = relu(MX @ [Wl;Wr] + bl) -> fp16 ----------------
__global__ void k_hgemm(const float* __restrict__ Wl, const float* __restrict__ Wr,
                        const float* __restrict__ bl) {
    __shared__ float As[16][132];   // [k][row], transposed
    __shared__ float Bs[16][64];
    int tid = threadIdx.x;
    int tx = tid & 15, ty = tid >> 4;
    int row0 = blockIdx.x * 128;
    float acc[8][4];
#pragma unroll
    for (int i = 0; i < 8; i++)
#pragma unroll
        for (int j = 0; j < 4; j++) acc[i][j] = 0.f;

    for (int kb = 0; kb < 256; kb += 16) {
        for (int l = tid; l < 512; l += 256) {
            int r = l >> 2, q = l & 3;
            float4 v = *(const float4*)&d_MX[(size_t)(row0 + r) * 256 + kb + q * 4];
            As[q * 4 + 0][r] = v.x; As[q * 4 + 1][r] = v.y;
            As[q * 4 + 2][r] = v.z; As[q * 4 + 3][r] = v.w;
        }
        {
            int k = tid >> 4, o4 = (tid & 15) * 4;
            int kg = kb + k;
            const float* Wsrc = (kg < 128) ? &Wl[kg * 64 + o4] : &Wr[(kg - 128) * 64 + o4];
            *(float4*)&Bs[k][o4] = *(const float4*)Wsrc;
        }
        __syncthreads();
#pragma unroll
        for (int k = 0; k < 16; k++) {
            float a[8], b[4];
#pragma unroll
            for (int i = 0; i < 8; i++) a[i] = As[k][ty * 8 + i];
#pragma unroll
            for (int j = 0; j < 4; j++) b[j] = Bs[k][tx * 4 + j];
#pragma unroll
            for (int i = 0; i < 8; i++)
#pragma unroll
                for (int j = 0; j < 4; j++) acc[i][j] += a[i] * b[j];
        }
        __syncthreads();
    }
#pragma unroll
    for (int i = 0; i < 8; i++)
#pragma unroll
        for (int j = 0; j < 4; j++) {
            int o = tx * 4 + j;
            d_Hh[(size_t)(row0 + ty * 8 + i) * 64 + o] =
                __float2half_rn(fmaxf(acc[i][j] + bl[o], 0.f));
        }
}

// ---------------- stage C: S = relu(ir @ Wir + bir) -> fp16 ----------------
__global__ void k_sgemm(const float* __restrict__ ir, const float* __restrict__ Wir,
                        const float* __restrict__ bir) {
    __shared__ float irs[64][32];
    __shared__ float Ws[32][128];
    int tid = threadIdx.x;
    int g0 = blockIdx.x * 64;
    for (int l = tid; l < 64 * 32; l += 256) irs[l >> 5][l & 31] = ir[(size_t)g0 * 32 + l];
    for (int l = tid; l < 32 * 128; l += 256) Ws[l >> 7][l & 127] = Wir[l];
    __syncthreads();
    int o = tid & 127, h = tid >> 7;
    float bo = bir[o];
    for (int gg = h; gg < 64; gg += 2) {
        float acc = bo;
#pragma unroll
        for (int k = 0; k < 32; k++) acc += irs[gg][k] * Ws[k][o];
        d_Sh[(size_t)(g0 + gg) * 128 + o] = __float2half_rn(fmaxf(acc, 0.f));
    }
}

// ---------------- stage D: decode GEMM, fp16 mma.sync m16n8k16 ----------------
// Z[8192,208] = A[8192,16384] @ W1, A[g, i*128+j] = P[g,i]*S[g,j].
// CTA: 128 graphs x 208 cols, K-half z (8192 K), 512 stages of k16.
// A-fragments built in registers from P (broadcast) * S (smem half2). B from smem ring.
#define NSTB 4
#define BROW 48                        // padded row stride (bytes), conflict-free
#define BSTG (208 * BROW)              // 9984 B per stage
#define SM_B 0
#define SM_S (NSTB * BSTG)             // 39936; 128 rows x 304B = 38912
#define SM_P (SM_S + 128 * 304)        // 78848; 128 rows x 136B = 17408
#define SM_TOTAL (SM_P + 128 * 136)    // 96256

__global__ void __launch_bounds__(256, 1)
k_decode() {
    extern __shared__ char smem[];
    uint32_t sb = su32(smem);
    int tid = threadIdx.x;
    int lane = tid & 31, warp = tid >> 5;
    int wm = warp >> 1, wn = warp & 1;
    int gq = lane >> 2, l4 = lane & 3;
    int m_base = wm * 32;
    int g0 = blockIdx.x * 128;
    int z  = blockIdx.y;

    // ---- fill S tile: rows g (stride 304B), 128 halfs = 256B each (16 x 16B)
    for (int l = tid; l < 2048; l += 256) {
        int row = l >> 4, c = l & 15;
        *(float4*)(smem + SM_S + row * 304 + c * 16) =
            *(const float4*)((const char*)d_Sh + (size_t)(g0 + row) * 256 + c * 16);
    }
    // ---- fill P tile: rows g (stride 136B), 64 halfs: P[g][i] = Hh[2(g0+g)+z][i]
    for (int l = tid; l < 2048; l += 256) {
        int row = l >> 4, c = l & 15;
        *(float2*)(smem + SM_P + row * 136 + c * 8) =
            *(const float2*)((const char*)d_Hh + ((size_t)(2 * (g0 + row) + z) * 64 + c * 4) * 2);
    }
    __syncthreads();

    // ---- B stage loader (cp.async, 16B); row = n (0..207), 32B of k data, stride 48B
    auto load_stage = [&](int buf, int s) {
        int kb = 8192 * z + (s >> 3) * 128 + (s & 7) * 16;
        for (int l = tid; l < 416; l += 256) {
            int row = l >> 1, hh = l & 1;
            uint32_t dst = sb + SM_B + buf * BSTG + row * BROW + hh * 16;
            const char* src = (const char*)(d_W1h + (size_t)row * 16384 + kb + hh * 8);
            asm volatile("cp.async.cg.shared.global [%0], [%1], 16;\n"
                         :: "r"(dst), "l"(src));
        }
        asm volatile("cp.async.commit_group;\n");
    };

    load_stage(0, 0); load_stage(1, 1); load_stage(2, 2);

    float acc[2][13][4];
#pragma unroll
    for (int a = 0; a < 2; a++)
#pragma unroll
        for (int b = 0; b < 13; b++)
#pragma unroll
            for (int c = 0; c < 4; c++) acc[a][b][c] = 0.f;

    __half2 pb[4];
    const int s_cb = (2 * l4) * 2;       // byte offset of j0 within row

    for (int s = 0; s < 512; s++) {
        asm volatile("cp.async.wait_group 2;\n" ::: "memory");
        __syncthreads();
        if (s + 3 < 512) load_stage((s + 3) & 3, s + 3);
        else asm volatile("cp.async.commit_group;\n");   // keep group accounting in tail

        if ((s & 7) == 0) {
            int i = s >> 3;
#pragma unroll
            for (int t = 0; t < 4; t++) {
                __half ph = *(const __half*)(smem + SM_P + (m_base + gq + 8 * t) * 136 + i * 2);
                pb[t] = __half2half2(ph);
            }
        }
        int jb = (s & 7) * 16;
        // A fragments
        uint32_t afr[2][4];
#pragma unroll
        for (int mt = 0; mt < 2; mt++) {
            const char* r0p = smem + SM_S + (m_base + mt * 16 + gq) * 304 + jb * 2 + s_cb;
            const char* r1p = r0p + 8 * 304;
            __half2 s00 = *(const __half2*)(r0p);
            __half2 s10 = *(const __half2*)(r1p);
            __half2 s01 = *(const __half2*)(r0p + 16);
            __half2 s11 = *(const __half2*)(r1p + 16);
            __half2 a0 = __hmul2(pb[mt * 2],     s00);
            __half2 a1 = __hmul2(pb[mt * 2 + 1], s10);
            __half2 a2 = __hmul2(pb[mt * 2],     s01);
            __half2 a3 = __hmul2(pb[mt * 2 + 1], s11);
            afr[mt][0] = *(uint32_t*)&a0; afr[mt][1] = *(uint32_t*)&a1;
            afr[mt][2] = *(uint32_t*)&a2; afr[mt][3] = *(uint32_t*)&a3;
        }
        const char* bst = smem + SM_B + (s & 3) * BSTG;
#pragma unroll
        for (int n8 = 0; n8 < 13; n8++) {
            const char* brow = bst + (wn * 104 + n8 * 8 + gq) * BROW + l4 * 4;
            uint32_t b0 = *(const uint32_t*)(brow);
            uint32_t b1 = *(const uint32_t*)(brow + 16);
#pragma unroll
            for (int mt = 0; mt < 2; mt++) {
                asm volatile(
                    "mma.sync.aligned.m16n8k16.row.col.f32.f16.f16.f32 "
                    "{%0,%1,%2,%3}, {%4,%5,%6,%7}, {%8,%9}, {%0,%1,%2,%3};"
                    : "+f"(acc[mt][n8][0]), "+f"(acc[mt][n8][1]),
                      "+f"(acc[mt][n8][2]), "+f"(acc[mt][n8][3])
                    : "r"(afr[mt][0]), "r"(afr[mt][1]), "r"(afr[mt][2]), "r"(afr[mt][3]),
                      "r"(b0), "r"(b1));
            }
        }
    }

    // ---- store partial tile
#pragma unroll
    for (int mt = 0; mt < 2; mt++) {
        int gr = g0 + m_base + mt * 16 + gq;
#pragma unroll
        for (int n8 = 0; n8 < 13; n8++) {
            int c0 = wn * 104 + n8 * 8 + 2 * l4;
            if (c0 < NOUT) {
                size_t b0 = ((size_t)z * GG + gr) * 208;
                size_t b1 = ((size_t)z * GG + gr + 8) * 208;
                *(float2*)&d_Zp[b0 + c0] = make_float2(acc[mt][n8][0], acc[mt][n8][1]);
                *(float2*)&d_Zp[b1 + c0] = make_float2(acc[mt][n8][2], acc[mt][n8][3]);
            }
        }
    }
}

// ---------------- epilogue: sum partials, bias+relu, @W2 ----------------
__global__ void k_final(const float* __restrict__ b1, const float* __restrict__ W2,
                        const float* __restrict__ b2, float* __restrict__ out) {
    int g = (blockIdx.x * blockDim.x + threadIdx.x) >> 5;
    int lane = threadIdx.x & 31;
    if (g >= GG) return;
    float a0 = 0.f, a1 = 0.f;
    for (int n = lane; n < NOUT; n += 32) {
        float v = b1[n];
#pragma unroll
        for (int zz = 0; zz < KS; zz++) v += d_Zp[((size_t)zz * GG + g) * 208 + n];
        v = fmaxf(v, 0.f);
        a0 += v * W2[n * 2];
        a1 += v * W2[n * 2 + 1];
    }
#pragma unroll
    for (int o = 16; o; o >>= 1) {
        a0 += __shfl_down_sync(0xffffffffu, a0, o);
        a1 += __shfl_down_sync(0xffffffffu, a1, o);
    }
    if (lane == 0) { out[g * 2] = a0 + b2[0]; out[g * 2 + 1] = a1 + b2[1]; }
}

// ---------------- host ----------------
extern "C" void kernel_launch(void* const* d_in, const int* in_sizes, int n_in,
                              void* d_out, int out_size) {
    const float* x       = (const float*)d_in[0];
    const int*   ei      = (const int*)d_in[1];
    const int*   set_idx = (const int*)d_in[2];
    const float* ir      = (const float*)d_in[4];
    const float* Wl      = (const float*)d_in[5];
    const float* bl      = (const float*)d_in[6];
    const float* Wr      = (const float*)d_in[7];
    const float* Wir     = (const float*)d_in[8];
    const float* bir     = (const float*)d_in[9];
    const float* W1      = (const float*)d_in[10];
    const float* b1      = (const float*)d_in[11];
    const float* W2      = (const float*)d_in[12];
    const float* b2      = (const float*)d_in[13];
    float* out = (float*)d_out;

    void *p_mark, *p_cnt, *p_cur;
    cudaGetSymbolAddress(&p_mark, d_mark);
    cudaGetSymbolAddress(&p_cnt,  d_cnt);
    cudaGetSymbolAddress(&p_cur,  d_cur);
    cudaMemsetAsync(p_mark, 0xFF, (size_t)NN * 4, 0);
    cudaMemsetAsync(p_cnt,  0,    (size_t)NSLOT * 4, 0);
    cudaMemsetAsync(p_cur,  0,    (size_t)NSLOT * 4, 0);

    k_prep<<<dim3(512, 7), dim3(32, 8)>>>(W1);
    k_mark<<<NSLOT / 256, 256>>>(set_idx);
    k_count<<<EE / 256, 256>>>(ei);
    k_scan<<<1, 1024>>>();
    k_fill<<<EE / 256, 256>>>(ei);
    k_agg<<<NSLOT / 8, 256>>>(x);
    k_fix<<<NSLOT / 8, 256>>>();
    k_hgemm<<<NSLOT / 128, 256>>>(Wl, Wr, bl);
    k_sgemm<<<GG / 64, 256>>>(ir, Wir, bir);

    cudaFuncSetAttribute(k_decode, cudaFuncAttributeMaxDynamicSharedMemorySize, SM_TOTAL);
    k_decode<<<dim3(GG / 128, KS), 256, SM_TOTAL>>>();

    k_final<<<(GG * 32 + 255) / 256, 256>>>(b1, W2, b2, out);
}

// round 7
// speedup vs baseline: 1.7597x; 1.0408x over previous
#include <cuda_runtime.h>
#include <cuda_fp16.h>
#include <cstdint>

// ---------------- problem constants (fixed shapes) ----------------
#define NN     131072      // nodes
#define EE     2097152     // edges
#define GG     8192        // graphs
#define NPG    16
#define NSLOT  16384       // 2 per graph
#define GS     64
#define NOUT   200
#define KS     2           // K-split for decode
#define ECAP   64          // per-slot edge bucket capacity

// ---------------- scratch (device globals; no runtime alloc) ----------------
__device__ int    d_mark[NN];
__device__ int    d_node_of[NSLOT];
__device__ int    d_cnt[NSLOT];
__device__ int    d_elist[NSLOT * ECAP];      // [slot][ECAP]
__device__ float  d_MX[NSLOT * 256];          // [slot][mean(128) | xv(128)]
__device__ __half d_Hh[NSLOT * GS];           // h per slot (fp16)
__device__ __half d_Sh[GG * 128];             // fused ir features (fp16)
__device__ __half d_W1h[208 * 16384];         // W1 transposed (n-major), fp16, zero-padded
__device__ float  d_Zp[(size_t)KS * GG * 208];// decode partials

__device__ __forceinline__ uint32_t su32(const void* p) {
    return (uint32_t)__cvta_generic_to_shared(p);
}

// ---------------- stage 0: W1 transpose + fp16 round ----------------
__global__ void k_prep(const float* __restrict__ W1) {
    __shared__ float tile[32][33];
    int kb = blockIdx.x * 32, nb = blockIdx.y * 32;
    int tx = threadIdx.x, ty = threadIdx.y;
#pragma unroll
    for (int r = 0; r < 4; r++) {
        int k = kb + ty + r * 8;
        int n = nb + tx;
        tile[ty + r * 8][tx] = (n < NOUT) ? W1[(size_t)k * NOUT + n] : 0.f;
    }
    __syncthreads();
#pragma unroll
    for (int r = 0; r < 4; r++) {
        int n = nb + ty + r * 8;
        if (n < 208) d_W1h[(size_t)n * 16384 + kb + tx] = __float2half_rn(tile[tx][ty + r * 8]);
    }
}

// ---------------- stage A: mark / bucket-fill / aggregate ----------------
__global__ void k_mark(const int* __restrict__ set_idx) {
    int s = blockIdx.x * blockDim.x + threadIdx.x;
    if (s >= NSLOT) return;
    int g = s >> 1, k = s & 1;
    int v = g * NPG + set_idx[g * 2 + k];
    d_node_of[s] = v;
    atomicMax(&d_mark[v], s);
}

// single pass: bucketed edge fill (no count/scan needed)
__global__ void k_fill(const int* __restrict__ ei) {
    int e = blockIdx.x * blockDim.x + threadIdx.x;
    if (e >= EE) return;
    int dst = ei[EE + e];
    int r = d_mark[dst];
    if (r >= 0) {
        int pos = atomicAdd(&d_cnt[r], 1);
        if (pos < ECAP) d_elist[r * ECAP + pos] = ei[e];
    }
}

__global__ void k_agg(const float* __restrict__ x) {
    int s = blockIdx.x * 8 + (threadIdx.x >> 5);
    int lane = threadIdx.x & 31;
    int v = d_node_of[s];
    if (d_mark[v] != s) return;                  // duplicate; filled by k_fix
    const float4* x4 = (const float4*)x;
    const int* el = &d_elist[s * ECAP];
    int n = d_cnt[s]; if (n > ECAP) n = ECAP;
    float4 acc = make_float4(0.f, 0.f, 0.f, 0.f);
    int i = 0;
    for (; i + 2 <= n; i += 2) {
        int s0 = el[i], s1 = el[i + 1];
        float4 t0 = x4[(size_t)s0 * 32 + lane];
        float4 t1 = x4[(size_t)s1 * 32 + lane];
        acc.x += t0.x + t1.x; acc.y += t0.y + t1.y;
        acc.z += t0.z + t1.z; acc.w += t0.w + t1.w;
    }
    if (i < n) {
        float4 t = x4[(size_t)el[i] * 32 + lane];
        acc.x += t.x; acc.y += t.y; acc.z += t.z; acc.w += t.w;
    }
    float inv = 1.f / (float)(n > 0 ? n : 1);
    acc.x *= inv; acc.y *= inv; acc.z *= inv; acc.w *= inv;
    float4* MX4 = (float4*)d_MX;
    MX4[(size_t)s * 64 + lane]      = acc;
    MX4[(size_t)s * 64 + 32 + lane] = x4[(size_t)v * 32 + lane];
}

__global__ void k_fix() {
    int s = blockIdx.x * 8 + (threadIdx.x >> 5);
    int lane = threadIdx.x & 31;
    int v = d_node_of[s];
    int rep = d_mark[v];
    if (rep == s) return;
    float4* MX4 = (float4*)d_MX;
    MX4[(size_t)s * 64 + lane]      = MX4[(size_t)rep * 64 + lane];
    MX4[(size_t)s * 64 + 32 + lane] = MX4[(size_t)rep * 64 + 32 + lane];
}

// ---------------- stage B: H = relu(MX @ [Wl;Wr] + bl) -> fp16 ----------------
__global__ void k_hgemm(const float* __restrict__ Wl, const float* __restrict__ Wr,
                        const float* __restrict__ bl) {
    __shared__ float As[16][132];   // [k][row], transposed
    __shared__ float Bs[16][64];
    int tid = threadIdx.x;
    int tx = tid & 15, ty = tid >> 4;
    int row0 = blockIdx.x * 128;
    float acc[8][4];
#pragma unroll
    for (int i = 0; i < 8; i++)
#pragma unroll
        for (int j = 0; j < 4; j++) acc[i][j] = 0.f;

    for (int kb = 0; kb < 256; kb += 16) {
        for (int l = tid; l < 512; l += 256) {
            int r = l >> 2, q = l & 3;
            float4 v = *(const float4*)&d_MX[(size_t)(row0 + r) * 256 + kb + q * 4];
            As[q * 4 + 0][r] = v.x; As[q * 4 + 1][r] = v.y;
            As[q * 4 + 2][r] = v.z; As[q * 4 + 3][r] = v.w;
        }
        {
            int k = tid >> 4, o4 = (tid & 15) * 4;
            int kg = kb + k;
            const float* Wsrc = (kg < 128) ? &Wl[kg * 64 + o4] : &Wr[(kg - 128) * 64 + o4];
            *(float4*)&Bs[k][o4] = *(const float4*)Wsrc;
        }
        __syncthreads();
#pragma unroll
        for (int k = 0; k < 16; k++) {
            float a[8], b[4];
#pragma unroll
            for (int i = 0; i < 8; i++) a[i] = As[k][ty * 8 + i];
#pragma unroll
            for (int j = 0; j < 4; j++) b[j] = Bs[k][tx * 4 + j];
#pragma unroll
            for (int i = 0; i < 8; i++)
#pragma unroll
                for (int j = 0; j < 4; j++) acc[i][j] += a[i] * b[j];
        }
        __syncthreads();
    }
#pragma unroll
    for (int i = 0; i < 8; i++)
#pragma unroll
        for (int j = 0; j < 4; j++) {
            int o = tx * 4 + j;
            d_Hh[(size_t)(row0 + ty * 8 + i) * 64 + o] =
                __float2half_rn(fmaxf(acc[i][j] + bl[o], 0.f));
        }
}

// ---------------- stage C: S = relu(ir @ Wir + bir) -> fp16 ----------------
__global__ void k_sgemm(const float* __restrict__ ir, const float* __restrict__ Wir,
                        const float* __restrict__ bir) {
    __shared__ float irs[64][32];
    __shared__ float Ws[32][128];
    int tid = threadIdx.x;
    int g0 = blockIdx.x * 64;
    for (int l = tid; l < 64 * 32; l += 256) irs[l >> 5][l & 31] = ir[(size_t)g0 * 32 + l];
    for (int l = tid; l < 32 * 128; l += 256) Ws[l >> 7][l & 127] = Wir[l];
    __syncthreads();
    int o = tid & 127, h = tid >> 7;
    float bo = bir[o];
    for (int gg = h; gg < 64; gg += 2) {
        float acc = bo;
#pragma unroll
        for (int k = 0; k < 32; k++) acc += irs[gg][k] * Ws[k][o];
        d_Sh[(size_t)(g0 + gg) * 128 + o] = __float2half_rn(fmaxf(acc, 0.f));
    }
}

// ---------------- stage D: decode GEMM, fp16 mma.sync m16n8k16 ----------------
// Z[8192,200] = A[8192,16384] @ W1, A[g, i*128+j] = P[g,i]*S[g,j].
// CTA: 128 graphs x 200 cols, K-half z, 512 stages of k16.
// Warp map: wm = warp&3 (SMSP id), wn = warp>>2 -> each SMSP has one 13-tile
// and one 12-tile warp (50 HMMA/SMSP/stage, balanced).
#define NSTB 4
#define BROW 48                        // padded row stride (bytes), conflict-free
#define BSTG (200 * BROW)              // 9600 B per stage
#define SM_B 0
#define SM_S (NSTB * BSTG)             // 38400; 128 rows x 304B = 38912
#define SM_P (SM_S + 128 * 304)        // 77312; 128 rows x 136B = 17408
#define SM_TOTAL (SM_P + 128 * 136)    // 94720

__global__ void __launch_bounds__(256, 1)
k_decode() {
    extern __shared__ char smem[];
    uint32_t sb = su32(smem);
    int tid = threadIdx.x;
    int lane = tid & 31, warp = tid >> 5;
    int wm = warp & 3, wn = warp >> 2;
    int gq = lane >> 2, l4 = lane & 3;
    int m_base = wm * 32;
    int g0 = blockIdx.x * 128;
    int z  = blockIdx.y;

    // ---- fill S tile: rows g (stride 304B), 128 halfs = 256B each (16 x 16B)
    for (int l = tid; l < 2048; l += 256) {
        int row = l >> 4, c = l & 15;
        *(float4*)(smem + SM_S + row * 304 + c * 16) =
            *(const float4*)((const char*)d_Sh + (size_t)(g0 + row) * 256 + c * 16);
    }
    // ---- fill P tile: rows g (stride 136B), 64 halfs: P[g][i] = Hh[2(g0+g)+z][i]
    for (int l = tid; l < 2048; l += 256) {
        int row = l >> 4, c = l & 15;
        *(float2*)(smem + SM_P + row * 136 + c * 8) =
            *(const float2*)((const char*)d_Hh + ((size_t)(2 * (g0 + row) + z) * 64 + c * 4) * 2);
    }
    __syncthreads();

    // ---- B stage loader (cp.async, 16B); row = n (0..199), 32B of k, stride 48B
    auto load_stage = [&](int buf, int s) {
        int kb = 8192 * z + (s >> 3) * 128 + (s & 7) * 16;
        for (int l = tid; l < 400; l += 256) {
            int row = l >> 1, hh = l & 1;
            uint32_t dst = sb + SM_B + buf * BSTG + row * BROW + hh * 16;
            const char* src = (const char*)(d_W1h + (size_t)row * 16384 + kb + hh * 8);
            asm volatile("cp.async.cg.shared.global [%0], [%1], 16;\n"
                         :: "r"(dst), "l"(src));
        }
        asm volatile("cp.async.commit_group;\n");
    };

    load_stage(0, 0); load_stage(1, 1); load_stage(2, 2);

    float acc[2][13][4];
#pragma unroll
    for (int a = 0; a < 2; a++)
#pragma unroll
        for (int b = 0; b < 13; b++)
#pragma unroll
            for (int c = 0; c < 4; c++) acc[a][b][c] = 0.f;

    __half2 pb[4];
    const int s_cb = (2 * l4) * 2;       // byte offset of j0 within row

    for (int s = 0; s < 512; s++) {
        asm volatile("cp.async.wait_group 2;\n" ::: "memory");
        __syncthreads();
        if (s + 3 < 512) load_stage((s + 3) & 3, s + 3);
        else asm volatile("cp.async.commit_group;\n");   // keep group accounting in tail

        if ((s & 7) == 0) {
            int i = s >> 3;
#pragma unroll
            for (int t = 0; t < 4; t++) {
                __half ph = *(const __half*)(smem + SM_P + (m_base + gq + 8 * t) * 136 + i * 2);
                pb[t] = __half2half2(ph);
            }
        }
        int jb = (s & 7) * 16;
        // A fragments
        uint32_t afr[2][4];
#pragma unroll
        for (int mt = 0; mt < 2; mt++) {
            const char* r0p = smem + SM_S + (m_base + mt * 16 + gq) * 304 + jb * 2 + s_cb;
            const char* r1p = r0p + 8 * 304;
            __half2 s00 = *(const __half2*)(r0p);
            __half2 s10 = *(const __half2*)(r1p);
            __half2 s01 = *(const __half2*)(r0p + 16);
            __half2 s11 = *(const __half2*)(r1p + 16);
            __half2 a0 = __hmul2(pb[mt * 2],     s00);
            __half2 a1 = __hmul2(pb[mt * 2 + 1], s10);
            __half2 a2 = __hmul2(pb[mt * 2],     s01);
            __half2 a3 = __hmul2(pb[mt * 2 + 1], s11);
            afr[mt][0] = *(uint32_t*)&a0; afr[mt][1] = *(uint32_t*)&a1;
            afr[mt][2] = *(uint32_t*)&a2; afr[mt][3] = *(uint32_t*)&a3;
        }
        const char* bst = smem + SM_B + (s & 3) * BSTG;

#define MMA_TILE(n8)                                                            \
        {                                                                       \
            const char* brow = bst + (wn * 104 + (n8) * 8 + gq) * BROW + l4 * 4;\
            uint32_t b0 = *(const uint32_t*)(brow);                             \
            uint32_t b1 = *(const uint32_t*)(brow + 16);                        \
            _Pragma("unroll")                                                   \
            for (int mt = 0; mt < 2; mt++) {                                    \
                asm volatile(                                                   \
                    "mma.sync.aligned.m16n8k16.row.col.f32.f16.f16.f32 "        \
                    "{%0,%1,%2,%3}, {%4,%5,%6,%7}, {%8,%9}, {%0,%1,%2,%3};"     \
                    : "+f"(acc[mt][n8][0]), "+f"(acc[mt][n8][1]),               \
                      "+f"(acc[mt][n8][2]), "+f"(acc[mt][n8][3])                \
                    : "r"(afr[mt][0]), "r"(afr[mt][1]),                         \
                      "r"(afr[mt][2]), "r"(afr[mt][3]),                         \
                      "r"(b0), "r"(b1));                                        \
            }                                                                   \
        }

#pragma unroll
        for (int n8 = 0; n8 < 12; n8++) MMA_TILE(n8)
        if (wn == 0) MMA_TILE(12)
#undef MMA_TILE
    }

    // ---- store partial tile
#pragma unroll
    for (int mt = 0; mt < 2; mt++) {
        int gr = g0 + m_base + mt * 16 + gq;
        size_t b0 = ((size_t)z * GG + gr) * 208;
        size_t b1 = ((size_t)z * GG + gr + 8) * 208;
#pragma unroll
        for (int n8 = 0; n8 < 12; n8++) {
            int c0 = wn * 104 + n8 * 8 + 2 * l4;
            *(float2*)&d_Zp[b0 + c0] = make_float2(acc[mt][n8][0], acc[mt][n8][1]);
            *(float2*)&d_Zp[b1 + c0] = make_float2(acc[mt][n8][2], acc[mt][n8][3]);
        }
        if (wn == 0) {
            int c0 = 96 + 2 * l4;
            *(float2*)&d_Zp[b0 + c0] = make_float2(acc[mt][12][0], acc[mt][12][1]);
            *(float2*)&d_Zp[b1 + c0] = make_float2(acc[mt][12][2], acc[mt][12][3]);
        }
    }
}

// ---------------- epilogue: sum partials, bias+relu, @W2 ----------------
__global__ void k_final(const float* __restrict__ b1, const float* __restrict__ W2,
                        const float* __restrict__ b2, float* __restrict__ out) {
    int g = (blockIdx.x * blockDim.x + threadIdx.x) >> 5;
    int lane = threadIdx.x & 31;
    if (g >= GG) return;
    float a0 = 0.f, a1 = 0.f;
    for (int n = lane; n < NOUT; n += 32) {
        float v = b1[n];
#pragma unroll
        for (int zz = 0; zz < KS; zz++) v += d_Zp[((size_t)zz * GG + g) * 208 + n];
        v = fmaxf(v, 0.f);
        a0 += v * W2[n * 2];
        a1 += v * W2[n * 2 + 1];
    }
#pragma unroll
    for (int o = 16; o; o >>= 1) {
        a0 += __shfl_down_sync(0xffffffffu, a0, o);
        a1 += __shfl_down_sync(0xffffffffu, a1, o);
    }
    if (lane == 0) { out[g * 2] = a0 + b2[0]; out[g * 2 + 1] = a1 + b2[1]; }
}

// ---------------- host ----------------
extern "C" void kernel_launch(void* const* d_in, const int* in_sizes, int n_in,
                              void* d_out, int out_size) {
    const float* x       = (const float*)d_in[0];
    const int*   ei      = (const int*)d_in[1];
    const int*   set_idx = (const int*)d_in[2];
    const float* ir      = (const float*)d_in[4];
    const float* Wl      = (const float*)d_in[5];
    const float* bl      = (const float*)d_in[6];
    const float* Wr      = (const float*)d_in[7];
    const float* Wir     = (const float*)d_in[8];
    const float* bir     = (const float*)d_in[9];
    const float* W1      = (const float*)d_in[10];
    const float* b1      = (const float*)d_in[11];
    const float* W2      = (const float*)d_in[12];
    const float* b2      = (const float*)d_in[13];
    float* out = (float*)d_out;

    void *p_mark, *p_cnt;
    cudaGetSymbolAddress(&p_mark, d_mark);
    cudaGetSymbolAddress(&p_cnt,  d_cnt);
    cudaMemsetAsync(p_mark, 0xFF, (size_t)NN * 4, 0);
    cudaMemsetAsync(p_cnt,  0,    (size_t)NSLOT * 4, 0);

    k_prep<<<dim3(512, 7), dim3(32, 8)>>>(W1);
    k_mark<<<NSLOT / 256, 256>>>(set_idx);
    k_fill<<<EE / 256, 256>>>(ei);
    k_agg<<<NSLOT / 8, 256>>>(x);
    k_fix<<<NSLOT / 8, 256>>>();
    k_hgemm<<<NSLOT / 128, 256>>>(Wl, Wr, bl);
    k_sgemm<<<GG / 64, 256>>>(ir, Wir, bir);

    cudaFuncSetAttribute(k_decode, cudaFuncAttributeMaxDynamicSharedMemorySize, SM_TOTAL);
    k_decode<<<dim3(GG / 128, KS), 256, SM_TOTAL>>>();

    k_final<<<(GG * 32 + 255) / 256, 256>>>(b1, W2, b2, out);
}

// round 10
// speedup vs baseline: 1.8528x; 1.0529x over previous
#include <cuda_runtime.h>
#include <cuda_fp16.h>
#include <cstdint>

// ---------------- problem constants (fixed shapes) ----------------
#define NN     131072      // nodes
#define EE     2097152     // edges
#define GG     8192        // graphs
#define NPG    16
#define NSLOT  16384       // 2 per graph
#define GS     64
#define NOUT   200
#define KS     2           // K-split for decode
#define ECAP   64          // per-slot edge bucket capacity

// ---------------- scratch (device globals; no runtime alloc) ----------------
__device__ int    d_mark[NN];
__device__ int    d_node_of[NSLOT];
__device__ int    d_cnt[NSLOT];
__device__ int    d_elist[NSLOT * ECAP];      // [slot][ECAP]
__device__ float  d_MX[NSLOT * 256];          // [slot][mean(128) | xv(128)]
__device__ __half d_Hh[NSLOT * GS];           // h per slot (fp16)
__device__ __half d_Sh[GG * 128];             // fused ir features (fp16)
__device__ __half d_W1h[208 * 16384];         // W1 transposed (n-major), fp16, zero-padded
__device__ float  d_Zp[(size_t)KS * GG * 208];// decode partials

__device__ __forceinline__ uint32_t su32(const void* p) {
    return (uint32_t)__cvta_generic_to_shared(p);
}

// ---------------- stage 0: W1 transpose + fp16 round ----------------
__global__ void k_prep(const float* __restrict__ W1) {
    __shared__ float tile[32][33];
    int kb = blockIdx.x * 32, nb = blockIdx.y * 32;
    int tx = threadIdx.x, ty = threadIdx.y;
#pragma unroll
    for (int r = 0; r < 4; r++) {
        int k = kb + ty + r * 8;
        int n = nb + tx;
        tile[ty + r * 8][tx] = (n < NOUT) ? W1[(size_t)k * NOUT + n] : 0.f;
    }
    __syncthreads();
#pragma unroll
    for (int r = 0; r < 4; r++) {
        int n = nb + ty + r * 8;
        if (n < 208) d_W1h[(size_t)n * 16384 + kb + tx] = __float2half_rn(tile[tx][ty + r * 8]);
    }
}

// ---------------- stage A: mark / bucket-fill / aggregate ----------------
__global__ void k_mark(const int* __restrict__ set_idx) {
    int s = blockIdx.x * blockDim.x + threadIdx.x;
    if (s >= NSLOT) return;
    int g = s >> 1, k = s & 1;
    int v = g * NPG + set_idx[g * 2 + k];
    d_node_of[s] = v;
    atomicMax(&d_mark[v], s);
}

// bucketed edge fill, 4 edges/thread for MLP
__global__ void k_fill(const int* __restrict__ ei) {
    int e0 = (blockIdx.x * blockDim.x + threadIdx.x) * 4;
    if (e0 >= EE) return;
    int4 dst4 = *(const int4*)&ei[EE + e0];
    int r0 = d_mark[dst4.x];
    int r1 = d_mark[dst4.y];
    int r2 = d_mark[dst4.z];
    int r3 = d_mark[dst4.w];
    if ((r0 & r1 & r2 & r3) < 0) return;         // ALL negative -> skip batch
    if (r0 >= 0) {
        int p = atomicAdd(&d_cnt[r0], 1);
        if (p < ECAP) d_elist[r0 * ECAP + p] = ei[e0];
    }
    if (r1 >= 0) {
        int p = atomicAdd(&d_cnt[r1], 1);
        if (p < ECAP) d_elist[r1 * ECAP + p] = ei[e0 + 1];
    }
    if (r2 >= 0) {
        int p = atomicAdd(&d_cnt[r2], 1);
        if (p < ECAP) d_elist[r2 * ECAP + p] = ei[e0 + 2];
    }
    if (r3 >= 0) {
        int p = atomicAdd(&d_cnt[r3], 1);
        if (p < ECAP) d_elist[r3 * ECAP + p] = ei[e0 + 3];
    }
}

__global__ void k_agg(const float* __restrict__ x) {
    int s = blockIdx.x * 8 + (threadIdx.x >> 5);
    int lane = threadIdx.x & 31;
    int v = d_node_of[s];
    if (d_mark[v] != s) return;                  // duplicate; filled by k_fix
    const float4* x4 = (const float4*)x;
    const int* el = &d_elist[s * ECAP];
    int deg = d_cnt[s];
    int n = deg > ECAP ? ECAP : deg;
    float4 acc = make_float4(0.f, 0.f, 0.f, 0.f);
    int i = 0;
    for (; i + 4 <= n; i += 4) {
        int s0 = el[i], s1 = el[i + 1], s2 = el[i + 2], s3 = el[i + 3];
        float4 t0 = x4[(size_t)s0 * 32 + lane];
        float4 t1 = x4[(size_t)s1 * 32 + lane];
        float4 t2 = x4[(size_t)s2 * 32 + lane];
        float4 t3 = x4[(size_t)s3 * 32 + lane];
        acc.x += (t0.x + t1.x) + (t2.x + t3.x);
        acc.y += (t0.y + t1.y) + (t2.y + t3.y);
        acc.z += (t0.z + t1.z) + (t2.z + t3.z);
        acc.w += (t0.w + t1.w) + (t2.w + t3.w);
    }
    for (; i < n; i++) {
        float4 t = x4[(size_t)el[i] * 32 + lane];
        acc.x += t.x; acc.y += t.y; acc.z += t.z; acc.w += t.w;
    }
    float inv = 1.f / (float)(deg > 0 ? deg : 1);
    acc.x *= inv; acc.y *= inv; acc.z *= inv; acc.w *= inv;
    float4* MX4 = (float4*)d_MX;
    MX4[(size_t)s * 64 + lane]      = acc;
    MX4[(size_t)s * 64 + 32 + lane] = x4[(size_t)v * 32 + lane];
}

__global__ void k_fix() {
    int s = blockIdx.x * 8 + (threadIdx.x >> 5);
    int lane = threadIdx.x & 31;
    int v = d_node_of[s];
    int rep = d_mark[v];
    if (rep == s) return;
    float4* MX4 = (float4*)d_MX;
    MX4[(size_t)s * 64 + lane]      = MX4[(size_t)rep * 64 + lane];
    MX4[(size_t)s * 64 + 32 + lane] = MX4[(size_t)rep * 64 + 32 + lane];
}

// ---------------- stage B: H = relu(MX @ [Wl;Wr] + bl) -> fp16 ----------------
__global__ void k_hgemm(const float* __restrict__ Wl, const float* __restrict__ Wr,
                        const float* __restrict__ bl) {
    __shared__ float As[16][132];   // [k][row], transposed
    __shared__ float Bs[16][64];
    int tid = threadIdx.x;
    int tx = tid & 15, ty = tid >> 4;
    int row0 = blockIdx.x * 128;
    float acc[8][4];
#pragma unroll
    for (int i = 0; i < 8; i++)
#pragma unroll
        for (int j = 0; j < 4; j++) acc[i][j] = 0.f;

    for (int kb = 0; kb < 256; kb += 16) {
        for (int l = tid; l < 512; l += 256) {
            int r = l >> 2, q = l & 3;
            float4 v = *(const float4*)&d_MX[(size_t)(row0 + r) * 256 + kb + q * 4];
            As[q * 4 + 0][r] = v.x; As[q * 4 + 1][r] = v.y;
            As[q * 4 + 2][r] = v.z; As[q * 4 + 3][r] = v.w;
        }
        {
            int k = tid >> 4, o4 = (tid & 15) * 4;
            int kg = kb + k;
            const float* Wsrc = (kg < 128) ? &Wl[kg * 64 + o4] : &Wr[(kg - 128) * 64 + o4];
            *(float4*)&Bs[k][o4] = *(const float4*)Wsrc;
        }
        __syncthreads();
#pragma unroll
        for (int k = 0; k < 16; k++) {
            float a[8], b[4];
#pragma unroll
            for (int i = 0; i < 8; i++) a[i] = As[k][ty * 8 + i];
#pragma unroll
            for (int j = 0; j < 4; j++) b[j] = Bs[k][tx * 4 + j];
#pragma unroll
            for (int i = 0; i < 8; i++)
#pragma unroll
                for (int j = 0; j < 4; j++) acc[i][j] += a[i] * b[j];
        }
        __syncthreads();
    }
#pragma unroll
    for (int i = 0; i < 8; i++)
#pragma unroll
        for (int j = 0; j < 4; j++) {
            int o = tx * 4 + j;
            d_Hh[(size_t)(row0 + ty * 8 + i) * 64 + o] =
                __float2half_rn(fmaxf(acc[i][j] + bl[o], 0.f));
        }
}

// ---------------- stage C: S = relu(ir @ Wir + bir) -> fp16 ----------------
__global__ void k_sgemm(const float* __restrict__ ir, const float* __restrict__ Wir,
                        const float* __restrict__ bir) {
    __shared__ float irs[64][32];
    __shared__ float Ws[32][128];
    int tid = threadIdx.x;
    int g0 = blockIdx.x * 64;
    for (int l = tid; l < 64 * 32; l += 256) irs[l >> 5][l & 31] = ir[(size_t)g0 * 32 + l];
    for (int l = tid; l < 32 * 128; l += 256) Ws[l >> 7][l & 127] = Wir[l];
    __syncthreads();
    int o = tid & 127, h = tid >> 7;
    float bo = bir[o];
    for (int gg = h; gg < 64; gg += 2) {
        float acc = bo;
#pragma unroll
        for (int k = 0; k < 32; k++) acc += irs[gg][k] * Ws[k][o];
        d_Sh[(size_t)(g0 + gg) * 128 + o] = __float2half_rn(fmaxf(acc, 0.f));
    }
}

// ---------------- stage D: decode GEMM, fp16 mma.sync m16n8k16 ----------------
// Z[8192,200] = A[8192,16384] @ W1, A[g, i*128+j] = P[g,i]*S[g,j].
// CTA: 128 graphs x 200 cols, K-half z, 512 stages of k16.
// Warp map: wm = warp&3 (SMSP id), wn = warp>>2 -> each SMSP has one 13-tile
// and one 12-tile warp (50 HMMA/SMSP/stage, balanced).
#define NSTB 4
#define BROW 48                        // padded row stride (bytes), conflict-free
#define BSTG (200 * BROW)              // 9600 B per stage
#define SM_B 0
#define SM_S (NSTB * BSTG)             // 38400; 128 rows x 304B = 38912
#define SM_P (SM_S + 128 * 304)        // 77312; 128 rows x 136B = 17408
#define SM_TOTAL (SM_P + 128 * 136)    // 94720

__global__ void __launch_bounds__(256, 1)
k_decode() {
    extern __shared__ char smem[];
    uint32_t sb = su32(smem);
    int tid = threadIdx.x;
    int lane = tid & 31, warp = tid >> 5;
    int wm = warp & 3, wn = warp >> 2;
    int gq = lane >> 2, l4 = lane & 3;
    int m_base = wm * 32;
    int g0 = blockIdx.x * 128;
    int z  = blockIdx.y;

    // ---- fill S tile: rows g (stride 304B), 128 halfs = 256B each (16 x 16B)
    for (int l = tid; l < 2048; l += 256) {
        int row = l >> 4, c = l & 15;
        *(float4*)(smem + SM_S + row * 304 + c * 16) =
            *(const float4*)((const char*)d_Sh + (size_t)(g0 + row) * 256 + c * 16);
    }
    // ---- fill P tile: rows g (stride 136B), 64 halfs: P[g][i] = Hh[2(g0+g)+z][i]
    for (int l = tid; l < 2048; l += 256) {
        int row = l >> 4, c = l & 15;
        *(float2*)(smem + SM_P + row * 136 + c * 8) =
            *(const float2*)((const char*)d_Hh + ((size_t)(2 * (g0 + row) + z) * 64 + c * 4) * 2);
    }
    __syncthreads();

    // ---- B stage loader (cp.async, 16B); row = n (0..199), 32B of k, stride 48B
    auto load_stage = [&](int buf, int s) {
        int kb = 8192 * z + (s >> 3) * 128 + (s & 7) * 16;
        for (int l = tid; l < 400; l += 256) {
            int row = l >> 1, hh = l & 1;
            uint32_t dst = sb + SM_B + buf * BSTG + row * BROW + hh * 16;
            const char* src = (const char*)(d_W1h + (size_t)row * 16384 + kb + hh * 8);
            asm volatile("cp.async.cg.shared.global [%0], [%1], 16;\n"
                         :: "r"(dst), "l"(src));
        }
        asm volatile("cp.async.commit_group;\n");
    };

    load_stage(0, 0); load_stage(1, 1); load_stage(2, 2);

    float acc[2][13][4];
#pragma unroll
    for (int a = 0; a < 2; a++)
#pragma unroll
        for (int b = 0; b < 13; b++)
#pragma unroll
            for (int c = 0; c < 4; c++) acc[a][b][c] = 0.f;

    __half2 pb[4];
    const int s_cb = (2 * l4) * 2;       // byte offset of j0 within row

    for (int s = 0; s < 512; s++) {
        asm volatile("cp.async.wait_group 2;\n" ::: "memory");
        __syncthreads();
        if (s + 3 < 512) load_stage((s + 3) & 3, s + 3);
        else asm volatile("cp.async.commit_group;\n");   // keep group accounting in tail

        if ((s & 7) == 0) {
            int i = s >> 3;
#pragma unroll
            for (int t = 0; t < 4; t++) {
                __half ph = *(const __half*)(smem + SM_P + (m_base + gq + 8 * t) * 136 + i * 2);
                pb[t] = __half2half2(ph);
            }
        }
        int jb = (s & 7) * 16;
        // A fragments
        uint32_t afr[2][4];
#pragma unroll
        for (int mt = 0; mt < 2; mt++) {
            const char* r0p = smem + SM_S + (m_base + mt * 16 + gq) * 304 + jb * 2 + s_cb;
            const char* r1p = r0p + 8 * 304;
            __half2 s00 = *(const __half2*)(r0p);
            __half2 s10 = *(const __half2*)(r1p);
            __half2 s01 = *(const __half2*)(r0p + 16);
            __half2 s11 = *(const __half2*)(r1p + 16);
            __half2 a0 = __hmul2(pb[mt * 2],     s00);
            __half2 a1 = __hmul2(pb[mt * 2 + 1], s10);
            __half2 a2 = __hmul2(pb[mt * 2],     s01);
            __half2 a3 = __hmul2(pb[mt * 2 + 1], s11);
            afr[mt][0] = *(uint32_t*)&a0; afr[mt][1] = *(uint32_t*)&a1;
            afr[mt][2] = *(uint32_t*)&a2; afr[mt][3] = *(uint32_t*)&a3;
        }
        const char* bst = smem + SM_B + (s & 3) * BSTG;

#define MMA_TILE(n8)                                                            \
        {                                                                       \
            const char* brow = bst + (wn * 104 + (n8) * 8 + gq) * BROW + l4 * 4;\
            uint32_t b0 = *(const uint32_t*)(brow);                             \
            uint32_t b1 = *(const uint32_t*)(brow + 16);                        \
            _Pragma("unroll")                                                   \
            for (int mt = 0; mt < 2; mt++) {                                    \
                asm volatile(                                                   \
                    "mma.sync.aligned.m16n8k16.row.col.f32.f16.f16.f32 "        \
                    "{%0,%1,%2,%3}, {%4,%5,%6,%7}, {%8,%9}, {%0,%1,%2,%3};"     \
                    : "+f"(acc[mt][n8][0]), "+f"(acc[mt][n8][1]),               \
                      "+f"(acc[mt][n8][2]), "+f"(acc[mt][n8][3])                \
                    : "r"(afr[mt][0]), "r"(afr[mt][1]),                         \
                      "r"(afr[mt][2]), "r"(afr[mt][3]),                         \
                      "r"(b0), "r"(b1));                                        \
            }                                                                   \
        }

#pragma unroll
        for (int n8 = 0; n8 < 12; n8++) MMA_TILE(n8)
        if (wn == 0) MMA_TILE(12)
#undef MMA_TILE
    }

    // ---- store partial tile
#pragma unroll
    for (int mt = 0; mt < 2; mt++) {
        int gr = g0 + m_base + mt * 16 + gq;
        size_t b0 = ((size_t)z * GG + gr) * 208;
        size_t b1 = ((size_t)z * GG + gr + 8) * 208;
#pragma unroll
        for (int n8 = 0; n8 < 12; n8++) {
            int c0 = wn * 104 + n8 * 8 + 2 * l4;
            *(float2*)&d_Zp[b0 + c0] = make_float2(acc[mt][n8][0], acc[mt][n8][1]);
            *(float2*)&d_Zp[b1 + c0] = make_float2(acc[mt][n8][2], acc[mt][n8][3]);
        }
        if (wn == 0) {
            int c0 = 96 + 2 * l4;
            *(float2*)&d_Zp[b0 + c0] = make_float2(acc[mt][12][0], acc[mt][12][1]);
            *(float2*)&d_Zp[b1 + c0] = make_float2(acc[mt][12][2], acc[mt][12][3]);
        }
    }
}

// ---------------- epilogue: sum partials, bias+relu, @W2 ----------------
__global__ void k_final(const float* __restrict__ b1, const float* __restrict__ W2,
                        const float* __restrict__ b2, float* __restrict__ out) {
    int g = (blockIdx.x * blockDim.x + threadIdx.x) >> 5;
    int lane = threadIdx.x & 31;
    if (g >= GG) return;
    float a0 = 0.f, a1 = 0.f;
    for (int n = lane; n < NOUT; n += 32) {
        float v = b1[n];
#pragma unroll
        for (int zz = 0; zz < KS; zz++) v += d_Zp[((size_t)zz * GG + g) * 208 + n];
        v = fmaxf(v, 0.f);
        a0 += v * W2[n * 2];
        a1 += v * W2[n * 2 + 1];
    }
#pragma unroll
    for (int o = 16; o; o >>= 1) {
        a0 += __shfl_down_sync(0xffffffffu, a0, o);
        a1 += __shfl_down_sync(0xffffffffu, a1, o);
    }
    if (lane == 0) { out[g * 2] = a0 + b2[0]; out[g * 2 + 1] = a1 + b2[1]; }
}

// ---------------- host ----------------
extern "C" void kernel_launch(void* const* d_in, const int* in_sizes, int n_in,
                              void* d_out, int out_size) {
    const float* x       = (const float*)d_in[0];
    const int*   ei      = (const int*)d_in[1];
    const int*   set_idx = (const int*)d_in[2];
    const float* ir      = (const float*)d_in[4];
    const float* Wl      = (const float*)d_in[5];
    const float* bl      = (const float*)d_in[6];
    const float* Wr      = (const float*)d_in[7];
    const float* Wir     = (const float*)d_in[8];
    const float* bir     = (const float*)d_in[9];
    const float* W1      = (const float*)d_in[10];
    const float* b1      = (const float*)d_in[11];
    const float* W2      = (const float*)d_in[12];
    const float* b2      = (const float*)d_in[13];
    float* out = (float*)d_out;

    // side streams + events for fork/join under graph capture (created once;
    // host-side resources only, no device memory)
    static cudaStream_t s1 = nullptr, s2 = nullptr;
    static cudaEvent_t ef = nullptr, e1 = nullptr, e2 = nullptr;
    if (!s1) {
        cudaStreamCreateWithFlags(&s1, cudaStreamNonBlocking);
        cudaStreamCreateWithFlags(&s2, cudaStreamNonBlocking);
        cudaEventCreateWithFlags(&ef, cudaEventDisableTiming);
        cudaEventCreateWithFlags(&e1, cudaEventDisableTiming);
        cudaEventCreateWithFlags(&e2, cudaEventDisableTiming);
        cudaFuncSetAttribute(k_decode, cudaFuncAttributeMaxDynamicSharedMemorySize, SM_TOTAL);
    }

    void *p_mark, *p_cnt;
    cudaGetSymbolAddress(&p_mark, d_mark);
    cudaGetSymbolAddress(&p_cnt,  d_cnt);
    cudaMemsetAsync(p_mark, 0xFF, (size_t)NN * 4, 0);
    cudaMemsetAsync(p_cnt,  0,    (size_t)NSLOT * 4, 0);

    // fork: independent stages on side streams
    cudaEventRecord(ef, 0);
    cudaStreamWaitEvent(s1, ef, 0);
    cudaStreamWaitEvent(s2, ef, 0);
    k_prep<<<dim3(512, 7), dim3(32, 8), 0, s1>>>(W1);
    k_sgemm<<<GG / 64, 256, 0, s2>>>(ir, Wir, bir);

    // main chain on origin stream
    k_mark<<<NSLOT / 256, 256>>>(set_idx);
    k_fill<<<EE / 1024, 256>>>(ei);
    k_agg<<<NSLOT / 8, 256>>>(x);
    k_fix<<<NSLOT / 8, 256>>>();
    k_hgemm<<<NSLOT / 128, 256>>>(Wl, Wr, bl);

    // join
    cudaEventRecord(e1, s1);
    cudaEventRecord(e2, s2);
    cudaStreamWaitEvent(0, e1, 0);
    cudaStreamWaitEvent(0, e2, 0);

    k_decode<<<dim3(GG / 128, KS), 256, SM_TOTAL>>>();
    k_final<<<(GG * 32 + 255) / 256, 256>>>(b1, W2, b2, out);
}

// round 11
// speedup vs baseline: 1.8680x; 1.0082x over previous
#include <cuda_runtime.h>
#include <cuda_fp16.h>
#include <cstdint>

// ---------------- problem constants (fixed shapes) ----------------
#define NN     131072      // nodes
#define EE     2097152     // edges
#define GG     8192        // graphs
#define NPG    16
#define NSLOT  16384       // 2 per graph
#define GS     64
#define NOUT   200
#define NSLOTS_ZP 4        // partial slots for decode
#define ECAP   64          // per-slot edge bucket capacity
#define NUNITS 8192        // 64 M-blocks x 128 K-chunks

// ---------------- scratch (device globals; no runtime alloc) ----------------
__device__ int    d_mark[NN];
__device__ int    d_node_of[NSLOT];
__device__ int    d_cnt[NSLOT];
__device__ int    d_elist[NSLOT * ECAP];      // [slot][ECAP]
__device__ float  d_MX[NSLOT * 256];          // [slot][mean(128) | xv(128)]
__device__ __half d_Hh[NSLOT * GS];           // h per slot (fp16)
__device__ __half d_Sh[GG * 128];             // fused ir features (fp16)
__device__ __half d_W1h[208 * 16384];         // W1 transposed (n-major), fp16, zero-padded
__device__ float  d_Zp[(size_t)NSLOTS_ZP * GG * 208]; // decode partials (4 slots)

__device__ __forceinline__ uint32_t su32(const void* p) {
    return (uint32_t)__cvta_generic_to_shared(p);
}

// ---------------- stage 0: W1 transpose + fp16 round ----------------
__global__ void k_prep(const float* __restrict__ W1) {
    __shared__ float tile[32][33];
    int kb = blockIdx.x * 32, nb = blockIdx.y * 32;
    int tx = threadIdx.x, ty = threadIdx.y;
#pragma unroll
    for (int r = 0; r < 4; r++) {
        int k = kb + ty + r * 8;
        int n = nb + tx;
        tile[ty + r * 8][tx] = (n < NOUT) ? W1[(size_t)k * NOUT + n] : 0.f;
    }
    __syncthreads();
#pragma unroll
    for (int r = 0; r < 4; r++) {
        int n = nb + ty + r * 8;
        if (n < 208) d_W1h[(size_t)n * 16384 + kb + tx] = __float2half_rn(tile[tx][ty + r * 8]);
    }
}

// ---------------- stage A: mark / bucket-fill / aggregate ----------------
__global__ void k_mark(const int* __restrict__ set_idx) {
    int s = blockIdx.x * blockDim.x + threadIdx.x;
    if (s >= NSLOT) return;
    int g = s >> 1, k = s & 1;
    int v = g * NPG + set_idx[g * 2 + k];
    d_node_of[s] = v;
    atomicMax(&d_mark[v], s);
}

// bucketed edge fill, 8 edges/thread for MLP
__global__ void k_fill(const int* __restrict__ ei) {
    int e0 = (blockIdx.x * blockDim.x + threadIdx.x) * 8;
    if (e0 >= EE) return;
    int4 a = *(const int4*)&ei[EE + e0];
    int4 b = *(const int4*)&ei[EE + e0 + 4];
    int r[8];
    r[0] = d_mark[a.x]; r[1] = d_mark[a.y]; r[2] = d_mark[a.z]; r[3] = d_mark[a.w];
    r[4] = d_mark[b.x]; r[5] = d_mark[b.y]; r[6] = d_mark[b.z]; r[7] = d_mark[b.w];
    int all = r[0] & r[1] & r[2] & r[3] & r[4] & r[5] & r[6] & r[7];
    if (all < 0) return;                         // ALL negative -> skip batch
#pragma unroll
    for (int q = 0; q < 8; q++) {
        if (r[q] >= 0) {
            int p = atomicAdd(&d_cnt[r[q]], 1);
            if (p < ECAP) d_elist[r[q] * ECAP + p] = ei[e0 + q];
        }
    }
}

__global__ void k_agg(const float* __restrict__ x) {
    int s = blockIdx.x * 8 + (threadIdx.x >> 5);
    int lane = threadIdx.x & 31;
    int v = d_node_of[s];
    if (d_mark[v] != s) return;                  // duplicate; filled by k_fix
    const float4* x4 = (const float4*)x;
    const int* el = &d_elist[s * ECAP];
    int deg = d_cnt[s];
    int n = deg > ECAP ? ECAP : deg;
    float4 acc = make_float4(0.f, 0.f, 0.f, 0.f);
    int i = 0;
    for (; i + 4 <= n; i += 4) {
        int s0 = el[i], s1 = el[i + 1], s2 = el[i + 2], s3 = el[i + 3];
        float4 t0 = x4[(size_t)s0 * 32 + lane];
        float4 t1 = x4[(size_t)s1 * 32 + lane];
        float4 t2 = x4[(size_t)s2 * 32 + lane];
        float4 t3 = x4[(size_t)s3 * 32 + lane];
        acc.x += (t0.x + t1.x) + (t2.x + t3.x);
        acc.y += (t0.y + t1.y) + (t2.y + t3.y);
        acc.z += (t0.z + t1.z) + (t2.z + t3.z);
        acc.w += (t0.w + t1.w) + (t2.w + t3.w);
    }
    for (; i < n; i++) {
        float4 t = x4[(size_t)el[i] * 32 + lane];
        acc.x += t.x; acc.y += t.y; acc.z += t.z; acc.w += t.w;
    }
    float inv = 1.f / (float)(deg > 0 ? deg : 1);
    acc.x *= inv; acc.y *= inv; acc.z *= inv; acc.w *= inv;
    float4* MX4 = (float4*)d_MX;
    MX4[(size_t)s * 64 + lane]      = acc;
    MX4[(size_t)s * 64 + 32 + lane] = x4[(size_t)v * 32 + lane];
}

__global__ void k_fix() {
    int s = blockIdx.x * 8 + (threadIdx.x >> 5);
    int lane = threadIdx.x & 31;
    int v = d_node_of[s];
    int rep = d_mark[v];
    if (rep == s) return;
    float4* MX4 = (float4*)d_MX;
    MX4[(size_t)s * 64 + lane]      = MX4[(size_t)rep * 64 + lane];
    MX4[(size_t)s * 64 + 32 + lane] = MX4[(size_t)rep * 64 + 32 + lane];
}

// ---------------- stage B: H = relu(MX @ [Wl;Wr] + bl) -> fp16 ----------------
__global__ void k_hgemm(const float* __restrict__ Wl, const float* __restrict__ Wr,
                        const float* __restrict__ bl) {
    __shared__ float As[16][132];   // [k][row], transposed
    __shared__ float Bs[16][64];
    int tid = threadIdx.x;
    int tx = tid & 15, ty = tid >> 4;
    int row0 = blockIdx.x * 128;
    float acc[8][4];
#pragma unroll
    for (int i = 0; i < 8; i++)
#pragma unroll
        for (int j = 0; j < 4; j++) acc[i][j] = 0.f;

    for (int kb = 0; kb < 256; kb += 16) {
        for (int l = tid; l < 512; l += 256) {
            int r = l >> 2, q = l & 3;
            float4 v = *(const float4*)&d_MX[(size_t)(row0 + r) * 256 + kb + q * 4];
            As[q * 4 + 0][r] = v.x; As[q * 4 + 1][r] = v.y;
            As[q * 4 + 2][r] = v.z; As[q * 4 + 3][r] = v.w;
        }
        {
            int k = tid >> 4, o4 = (tid & 15) * 4;
            int kg = kb + k;
            const float* Wsrc = (kg < 128) ? &Wl[kg * 64 + o4] : &Wr[(kg - 128) * 64 + o4];
            *(float4*)&Bs[k][o4] = *(const float4*)Wsrc;
        }
        __syncthreads();
#pragma unroll
        for (int k = 0; k < 16; k++) {
            float a[8], b[4];
#pragma unroll
            for (int i = 0; i < 8; i++) a[i] = As[k][ty * 8 + i];
#pragma unroll
            for (int j = 0; j < 4; j++) b[j] = Bs[k][tx * 4 + j];
#pragma unroll
            for (int i = 0; i < 8; i++)
#pragma unroll
                for (int j = 0; j < 4; j++) acc[i][j] += a[i] * b[j];
        }
        __syncthreads();
    }
#pragma unroll
    for (int i = 0; i < 8; i++)
#pragma unroll
        for (int j = 0; j < 4; j++) {
            int o = tx * 4 + j;
            d_Hh[(size_t)(row0 + ty * 8 + i) * 64 + o] =
                __float2half_rn(fmaxf(acc[i][j] + bl[o], 0.f));
        }
}

// ---------------- stage C: S = relu(ir @ Wir + bir) -> fp16 ----------------
__global__ void k_sgemm(const float* __restrict__ ir, const float* __restrict__ Wir,
                        const float* __restrict__ bir) {
    __shared__ float irs[64][32];
    __shared__ float Ws[32][128];
    int tid = threadIdx.x;
    int g0 = blockIdx.x * 64;
    for (int l = tid; l < 64 * 32; l += 256) irs[l >> 5][l & 31] = ir[(size_t)g0 * 32 + l];
    for (int l = tid; l < 32 * 128; l += 256) Ws[l >> 7][l & 127] = Wir[l];
    __syncthreads();
    int o = tid & 127, h = tid >> 7;
    float bo = bir[o];
    for (int gg = h; gg < 64; gg += 2) {
        float acc = bo;
#pragma unroll
        for (int k = 0; k < 32; k++) acc += irs[gg][k] * Ws[k][o];
        d_Sh[(size_t)(g0 + gg) * 128 + o] = __float2half_rn(fmaxf(acc, 0.f));
    }
}

// ---------------- stage D: balanced persistent decode GEMM (fp16 m16n8k16) ----
// Z[8192,200] = A[8192,16384] @ W1, A[g, i*128+j] = P[g,i]*S[g,j].
// Work = 8192 units (64 M-blocks x 128 K-chunks of 128). CTA c of NC takes
// units [c*8192/NC, (c+1)*8192/NC) — spans <=2 M-blocks; partials flushed to
// d_Zp[slot = c&3] (covering CTAs of a block are <=4 consecutive ints).
#define NSTB 4
#define BROW 48                        // padded B row stride (bytes)
#define BSTG (200 * BROW)              // 9600 B per stage
#define SM_B 0
#define SM_S (NSTB * BSTG)             // 38400; S: 128 rows x 304B = 38912
#define SM_P (SM_S + 128 * 304)        // 77312; P: 128 rows x 264B = 33792
#define SM_TOTAL (SM_P + 128 * 264)    // 111104

__global__ void __launch_bounds__(256, 1)
k_decode() {
    extern __shared__ char smem[];
    uint32_t sb = su32(smem);
    int tid = threadIdx.x;
    int lane = tid & 31, warp = tid >> 5;
    int wm = warp & 3, wn = warp >> 2;
    int gq = lane >> 2, l4 = lane & 3;
    int m_base = wm * 32;
    int c = blockIdx.x, NC = gridDim.x;
    int u0 = (c * NUNITS) / NC;
    int u1 = ((c + 1) * NUNITS) / NC;
    int T = (u1 - u0) * 8;
    int m = u0 >> 7;

    // ---- tile loaders
    auto load_tiles = [&](int mb) {
        int g0 = mb * 128;
        // S: rows g (stride 304B), 128 halfs = 256B each
        for (int l = tid; l < 2048; l += 256) {
            int row = l >> 4, cc = l & 15;
            *(float4*)(smem + SM_S + row * 304 + cc * 16) =
                *(const float4*)((const char*)d_Sh + (size_t)(g0 + row) * 256 + cc * 16);
        }
        // P: rows g (stride 264B), 128 halfs: P[g][i] = Hh[2(g0+g)+(i>=64)][i&63]
        for (int l = tid; l < 4096; l += 256) {
            int row = l >> 5, grp = l & 31;          // grp: 4-half (8B) group
            *(float2*)(smem + SM_P + row * 264 + grp * 8) =
                *(const float2*)((const char*)d_Hh +
                    ((size_t)(2 * (g0 + row) + (grp >> 4)) * 64 + (grp & 15) * 4) * 2);
        }
    };
    // ---- B stage loader (cp.async); stage t -> k = (unit&127)*128 + (t&7)*16
    auto load_stage = [&](int buf, int t) {
        int iu = (u0 + (t >> 3)) & 127;
        int kb = iu * 128 + (t & 7) * 16;
        for (int l = tid; l < 400; l += 256) {
            int row = l >> 1, hh = l & 1;
            uint32_t dst = sb + SM_B + buf * BSTG + row * BROW + hh * 16;
            const char* src = (const char*)(d_W1h + (size_t)row * 16384 + kb + hh * 8);
            asm volatile("cp.async.cg.shared.global [%0], [%1], 16;\n"
                         :: "r"(dst), "l"(src));
        }
        asm volatile("cp.async.commit_group;\n");
    };

    float acc[2][13][4];
#pragma unroll
    for (int a = 0; a < 2; a++)
#pragma unroll
        for (int b = 0; b < 13; b++)
#pragma unroll
            for (int q = 0; q < 4; q++) acc[a][b][q] = 0.f;

    auto flush = [&](int mb) {
        int slot = c & 3;
#pragma unroll
        for (int mt = 0; mt < 2; mt++) {
            int gr = mb * 128 + m_base + mt * 16 + gq;
            size_t b0 = ((size_t)slot * GG + gr) * 208;
            size_t b1 = ((size_t)slot * GG + gr + 8) * 208;
#pragma unroll
            for (int n8 = 0; n8 < 12; n8++) {
                int c0 = wn * 104 + n8 * 8 + 2 * l4;
                *(float2*)&d_Zp[b0 + c0] = make_float2(acc[mt][n8][0], acc[mt][n8][1]);
                *(float2*)&d_Zp[b1 + c0] = make_float2(acc[mt][n8][2], acc[mt][n8][3]);
            }
            if (wn == 0) {
                int c0 = 96 + 2 * l4;
                *(float2*)&d_Zp[b0 + c0] = make_float2(acc[mt][12][0], acc[mt][12][1]);
                *(float2*)&d_Zp[b1 + c0] = make_float2(acc[mt][12][2], acc[mt][12][3]);
            }
        }
#pragma unroll
        for (int a = 0; a < 2; a++)
#pragma unroll
            for (int b = 0; b < 13; b++)
#pragma unroll
                for (int q = 0; q < 4; q++) acc[a][b][q] = 0.f;
    };

    load_tiles(m);
    __syncthreads();
    load_stage(0, 0); load_stage(1, 1); load_stage(2, 2);

    __half2 pb[4];
    const int s_cb = (2 * l4) * 2;       // byte offset of j0 within S row

    for (int t = 0; t < T; t++) {
        int u = u0 + (t >> 3);
        int mblk = u >> 7;
        if (mblk != m) {
            flush(m);                    // registers -> global; smem untouched
            __syncthreads();             // all warps done reading old tiles
            load_tiles(mblk);
            __syncthreads();
            m = mblk;
        }
        asm volatile("cp.async.wait_group 2;\n" ::: "memory");
        __syncthreads();
        if (t + 3 < T) load_stage((t + 3) & 3, t + 3);
        else asm volatile("cp.async.commit_group;\n");

        int sub = t & 7;
        if (sub == 0) {
            int iu = u & 127;
#pragma unroll
            for (int t4 = 0; t4 < 4; t4++) {
                __half ph = *(const __half*)(smem + SM_P + (m_base + gq + 8 * t4) * 264 + iu * 2);
                pb[t4] = __half2half2(ph);
            }
        }
        int jb = sub * 16;
        // A fragments
        uint32_t afr[2][4];
#pragma unroll
        for (int mt = 0; mt < 2; mt++) {
            const char* r0p = smem + SM_S + (m_base + mt * 16 + gq) * 304 + jb * 2 + s_cb;
            const char* r1p = r0p + 8 * 304;
            __half2 s00 = *(const __half2*)(r0p);
            __half2 s10 = *(const __half2*)(r1p);
            __half2 s01 = *(const __half2*)(r0p + 16);
            __half2 s11 = *(const __half2*)(r1p + 16);
            __half2 a0 = __hmul2(pb[mt * 2],     s00);
            __half2 a1 = __hmul2(pb[mt * 2 + 1], s10);
            __half2 a2 = __hmul2(pb[mt * 2],     s01);
            __half2 a3 = __hmul2(pb[mt * 2 + 1], s11);
            afr[mt][0] = *(uint32_t*)&a0; afr[mt][1] = *(uint32_t*)&a1;
            afr[mt][2] = *(uint32_t*)&a2; afr[mt][3] = *(uint32_t*)&a3;
        }
        const char* bst = smem + SM_B + (t & 3) * BSTG;

#define MMA_TILE(n8)                                                            \
        {                                                                       \
            const char* brow = bst + (wn * 104 + (n8) * 8 + gq) * BROW + l4 * 4;\
            uint32_t b0 = *(const uint32_t*)(brow);                             \
            uint32_t b1 = *(const uint32_t*)(brow + 16);                        \
            _Pragma("unroll")                                                   \
            for (int mt = 0; mt < 2; mt++) {                                    \
                asm volatile(                                                   \
                    "mma.sync.aligned.m16n8k16.row.col.f32.f16.f16.f32 "        \
                    "{%0,%1,%2,%3}, {%4,%5,%6,%7}, {%8,%9}, {%0,%1,%2,%3};"     \
                    : "+f"(acc[mt][n8][0]), "+f"(acc[mt][n8][1]),               \
                      "+f"(acc[mt][n8][2]), "+f"(acc[mt][n8][3])                \
                    : "r"(afr[mt][0]), "r"(afr[mt][1]),                         \
                      "r"(afr[mt][2]), "r"(afr[mt][3]),                         \
                      "r"(b0), "r"(b1));                                        \
            }                                                                   \
        }

#pragma unroll
        for (int n8 = 0; n8 < 12; n8++) MMA_TILE(n8)
        if (wn == 0) MMA_TILE(12)
#undef MMA_TILE
    }

    flush(m);
}

// ---------------- epilogue: sum 4 partial slots, bias+relu, @W2 ----------------
__global__ void k_final(const float* __restrict__ b1, const float* __restrict__ W2,
                        const float* __restrict__ b2, float* __restrict__ out) {
    int g = (blockIdx.x * blockDim.x + threadIdx.x) >> 5;
    int lane = threadIdx.x & 31;
    if (g >= GG) return;
    float a0 = 0.f, a1 = 0.f;
    for (int n = lane; n < NOUT; n += 32) {
        float v = b1[n];
#pragma unroll
        for (int zz = 0; zz < NSLOTS_ZP; zz++) v += d_Zp[((size_t)zz * GG + g) * 208 + n];
        v = fmaxf(v, 0.f);
        a0 += v * W2[n * 2];
        a1 += v * W2[n * 2 + 1];
    }
#pragma unroll
    for (int o = 16; o; o >>= 1) {
        a0 += __shfl_down_sync(0xffffffffu, a0, o);
        a1 += __shfl_down_sync(0xffffffffu, a1, o);
    }
    if (lane == 0) { out[g * 2] = a0 + b2[0]; out[g * 2 + 1] = a1 + b2[1]; }
}

// ---------------- host ----------------
extern "C" void kernel_launch(void* const* d_in, const int* in_sizes, int n_in,
                              void* d_out, int out_size) {
    const float* x       = (const float*)d_in[0];
    const int*   ei      = (const int*)d_in[1];
    const int*   set_idx = (const int*)d_in[2];
    const float* ir      = (const float*)d_in[4];
    const float* Wl      = (const float*)d_in[5];
    const float* bl      = (const float*)d_in[6];
    const float* Wr      = (const float*)d_in[7];
    const float* Wir     = (const float*)d_in[8];
    const float* bir     = (const float*)d_in[9];
    const float* W1      = (const float*)d_in[10];
    const float* b1      = (const float*)d_in[11];
    const float* W2      = (const float*)d_in[12];
    const float* b2      = (const float*)d_in[13];
    float* out = (float*)d_out;

    // one-time host-side setup (streams/events are host resources, no dev mem)
    static cudaStream_t s1 = nullptr, s2 = nullptr;
    static cudaEvent_t ef = nullptr, e1 = nullptr, e2 = nullptr;
    static int nsm = 0;
    if (!s1) {
        cudaStreamCreateWithFlags(&s1, cudaStreamNonBlocking);
        cudaStreamCreateWithFlags(&s2, cudaStreamNonBlocking);
        cudaEventCreateWithFlags(&ef, cudaEventDisableTiming);
        cudaEventCreateWithFlags(&e1, cudaEventDisableTiming);
        cudaEventCreateWithFlags(&e2, cudaEventDisableTiming);
        cudaFuncSetAttribute(k_decode, cudaFuncAttributeMaxDynamicSharedMemorySize, SM_TOTAL);
        cudaDeviceGetAttribute(&nsm, cudaDevAttrMultiProcessorCount, 0);
        if (nsm < 4) nsm = 4;
    }

    void *p_mark, *p_cnt, *p_zp;
    cudaGetSymbolAddress(&p_mark, d_mark);
    cudaGetSymbolAddress(&p_cnt,  d_cnt);
    cudaGetSymbolAddress(&p_zp,   d_Zp);
    cudaMemsetAsync(p_mark, 0xFF, (size_t)NN * 4, 0);
    cudaMemsetAsync(p_cnt,  0,    (size_t)NSLOT * 4, 0);

    // fork: independent stages on side streams
    cudaEventRecord(ef, 0);
    cudaStreamWaitEvent(s1, ef, 0);
    cudaStreamWaitEvent(s2, ef, 0);
    cudaMemsetAsync(p_zp, 0, (size_t)NSLOTS_ZP * GG * 208 * 4, s1);
    k_prep<<<dim3(512, 7), dim3(32, 8), 0, s1>>>(W1);
    k_sgemm<<<GG / 64, 256, 0, s2>>>(ir, Wir, bir);

    // main chain on origin stream
    k_mark<<<NSLOT / 256, 256>>>(set_idx);
    k_fill<<<EE / 2048, 256>>>(ei);
    k_agg<<<NSLOT / 8, 256>>>(x);
    k_fix<<<NSLOT / 8, 256>>>();
    k_hgemm<<<NSLOT / 128, 256>>>(Wl, Wr, bl);

    // join
    cudaEventRecord(e1, s1);
    cudaEventRecord(e2, s2);
    cudaStreamWaitEvent(0, e1, 0);
    cudaStreamWaitEvent(0, e2, 0);

    k_decode<<<nsm, 256, SM_TOTAL>>>();
    k_final<<<(GG * 32 + 255) / 256, 256>>>(b1, W2, b2, out);
}

// round 12
// speedup vs baseline: 1.8945x; 1.0142x over previous
#include <cuda_runtime.h>
#include <cuda_fp16.h>
#include <cstdint>

// ---------------- problem constants (fixed shapes) ----------------
#define NN     131072      // nodes
#define EE     2097152     // edges
#define GG     8192        // graphs
#define NPG    16
#define NSLOT  16384       // 2 per graph
#define GS     64
#define NOUT   200
#define NSLOTS_ZP 4        // partial slots for decode
#define ECAP   64          // per-slot edge bucket capacity
#define NUNITS 8192        // 64 M-blocks x 128 K-chunks

// ---------------- scratch (device globals; no runtime alloc) ----------------
__device__ int    d_mark[NN];
__device__ int    d_node_of[NSLOT];
__device__ int    d_cnt[NSLOT];
__device__ int    d_elist[NSLOT * ECAP];      // [slot][ECAP]
__device__ float  d_MX[NSLOT * 256];          // [slot][mean(128) | xv(128)]
__device__ __half d_Hh[NSLOT * GS];           // h per slot (fp16)
__device__ __half d_Sh[GG * 128];             // fused ir features (fp16)
__device__ __half d_W1h[208 * 16384];         // W1 transposed (n-major), fp16, zero-padded
__device__ float  d_Zp[(size_t)NSLOTS_ZP * GG * 208]; // decode partials (4 slots)

__device__ __forceinline__ uint32_t su32(const void* p) {
    return (uint32_t)__cvta_generic_to_shared(p);
}

// ---------------- stage 0: W1 transpose + fp16 round ----------------
__global__ void k_prep(const float* __restrict__ W1) {
    __shared__ float tile[32][33];
    int kb = blockIdx.x * 32, nb = blockIdx.y * 32;
    int tx = threadIdx.x, ty = threadIdx.y;
#pragma unroll
    for (int r = 0; r < 4; r++) {
        int k = kb + ty + r * 8;
        int n = nb + tx;
        tile[ty + r * 8][tx] = (n < NOUT) ? W1[(size_t)k * NOUT + n] : 0.f;
    }
    __syncthreads();
#pragma unroll
    for (int r = 0; r < 4; r++) {
        int n = nb + ty + r * 8;
        if (n < 208) d_W1h[(size_t)n * 16384 + kb + tx] = __float2half_rn(tile[tx][ty + r * 8]);
    }
}

// ---------------- stage A: mark / bucket-fill / aggregate ----------------
__global__ void k_mark(const int* __restrict__ set_idx) {
    int s = blockIdx.x * blockDim.x + threadIdx.x;
    if (s >= NSLOT) return;
    int g = s >> 1, k = s & 1;
    int v = g * NPG + set_idx[g * 2 + k];
    d_node_of[s] = v;
    atomicMax(&d_mark[v], s);
}

// bucketed edge fill, 8 edges/thread for MLP
__global__ void k_fill(const int* __restrict__ ei) {
    int e0 = (blockIdx.x * blockDim.x + threadIdx.x) * 8;
    if (e0 >= EE) return;
    int4 a = *(const int4*)&ei[EE + e0];
    int4 b = *(const int4*)&ei[EE + e0 + 4];
    int r[8];
    r[0] = d_mark[a.x]; r[1] = d_mark[a.y]; r[2] = d_mark[a.z]; r[3] = d_mark[a.w];
    r[4] = d_mark[b.x]; r[5] = d_mark[b.y]; r[6] = d_mark[b.z]; r[7] = d_mark[b.w];
    int all = r[0] & r[1] & r[2] & r[3] & r[4] & r[5] & r[6] & r[7];
    if (all < 0) return;                         // ALL negative -> skip batch
#pragma unroll
    for (int q = 0; q < 8; q++) {
        if (r[q] >= 0) {
            int p = atomicAdd(&d_cnt[r[q]], 1);
            if (p < ECAP) d_elist[r[q] * ECAP + p] = ei[e0 + q];
        }
    }
}

__global__ void k_agg(const float* __restrict__ x) {
    int s = blockIdx.x * 8 + (threadIdx.x >> 5);
    int lane = threadIdx.x & 31;
    int v = d_node_of[s];
    if (d_mark[v] != s) return;                  // duplicate; filled by k_fix
    const float4* x4 = (const float4*)x;
    const int* el = &d_elist[s * ECAP];
    int deg = d_cnt[s];
    int n = deg > ECAP ? ECAP : deg;
    float4 acc = make_float4(0.f, 0.f, 0.f, 0.f);
    int i = 0;
    for (; i + 4 <= n; i += 4) {
        int s0 = el[i], s1 = el[i + 1], s2 = el[i + 2], s3 = el[i + 3];
        float4 t0 = x4[(size_t)s0 * 32 + lane];
        float4 t1 = x4[(size_t)s1 * 32 + lane];
        float4 t2 = x4[(size_t)s2 * 32 + lane];
        float4 t3 = x4[(size_t)s3 * 32 + lane];
        acc.x += (t0.x + t1.x) + (t2.x + t3.x);
        acc.y += (t0.y + t1.y) + (t2.y + t3.y);
        acc.z += (t0.z + t1.z) + (t2.z + t3.z);
        acc.w += (t0.w + t1.w) + (t2.w + t3.w);
    }
    for (; i < n; i++) {
        float4 t = x4[(size_t)el[i] * 32 + lane];
        acc.x += t.x; acc.y += t.y; acc.z += t.z; acc.w += t.w;
    }
    float inv = 1.f / (float)(deg > 0 ? deg : 1);
    acc.x *= inv; acc.y *= inv; acc.z *= inv; acc.w *= inv;
    float4* MX4 = (float4*)d_MX;
    MX4[(size_t)s * 64 + lane]      = acc;
    MX4[(size_t)s * 64 + 32 + lane] = x4[(size_t)v * 32 + lane];
}

__global__ void k_fix() {
    int s = blockIdx.x * 8 + (threadIdx.x >> 5);
    int lane = threadIdx.x & 31;
    int v = d_node_of[s];
    int rep = d_mark[v];
    if (rep == s) return;
    float4* MX4 = (float4*)d_MX;
    MX4[(size_t)s * 64 + lane]      = MX4[(size_t)rep * 64 + lane];
    MX4[(size_t)s * 64 + 32 + lane] = MX4[(size_t)rep * 64 + 32 + lane];
}

// ---------------- stage B: H = relu(MX @ [Wl;Wr] + bl) -> fp16 ----------------
__global__ void k_hgemm(const float* __restrict__ Wl, const float* __restrict__ Wr,
                        const float* __restrict__ bl) {
    __shared__ float As[16][132];   // [k][row], transposed
    __shared__ float Bs[16][64];
    int tid = threadIdx.x;
    int tx = tid & 15, ty = tid >> 4;
    int row0 = blockIdx.x * 128;
    float acc[8][4];
#pragma unroll
    for (int i = 0; i < 8; i++)
#pragma unroll
        for (int j = 0; j < 4; j++) acc[i][j] = 0.f;

    for (int kb = 0; kb < 256; kb += 16) {
        for (int l = tid; l < 512; l += 256) {
            int r = l >> 2, q = l & 3;
            float4 v = *(const float4*)&d_MX[(size_t)(row0 + r) * 256 + kb + q * 4];
            As[q * 4 + 0][r] = v.x; As[q * 4 + 1][r] = v.y;
            As[q * 4 + 2][r] = v.z; As[q * 4 + 3][r] = v.w;
        }
        {
            int k = tid >> 4, o4 = (tid & 15) * 4;
            int kg = kb + k;
            const float* Wsrc = (kg < 128) ? &Wl[kg * 64 + o4] : &Wr[(kg - 128) * 64 + o4];
            *(float4*)&Bs[k][o4] = *(const float4*)Wsrc;
        }
        __syncthreads();
#pragma unroll
        for (int k = 0; k < 16; k++) {
            float a[8], b[4];
#pragma unroll
            for (int i = 0; i < 8; i++) a[i] = As[k][ty * 8 + i];
#pragma unroll
            for (int j = 0; j < 4; j++) b[j] = Bs[k][tx * 4 + j];
#pragma unroll
            for (int i = 0; i < 8; i++)
#pragma unroll
                for (int j = 0; j < 4; j++) acc[i][j] += a[i] * b[j];
        }
        __syncthreads();
    }
#pragma unroll
    for (int i = 0; i < 8; i++)
#pragma unroll
        for (int j = 0; j < 4; j++) {
            int o = tx * 4 + j;
            d_Hh[(size_t)(row0 + ty * 8 + i) * 64 + o] =
                __float2half_rn(fmaxf(acc[i][j] + bl[o], 0.f));
        }
}

// ---------------- stage C: S = relu(ir @ Wir + bir) -> fp16 ----------------
__global__ void k_sgemm(const float* __restrict__ ir, const float* __restrict__ Wir,
                        const float* __restrict__ bir) {
    __shared__ float irs[64][32];
    __shared__ float Ws[32][128];
    int tid = threadIdx.x;
    int g0 = blockIdx.x * 64;
    for (int l = tid; l < 64 * 32; l += 256) irs[l >> 5][l & 31] = ir[(size_t)g0 * 32 + l];
    for (int l = tid; l < 32 * 128; l += 256) Ws[l >> 7][l & 127] = Wir[l];
    __syncthreads();
    int o = tid & 127, h = tid >> 7;
    float bo = bir[o];
    for (int gg = h; gg < 64; gg += 2) {
        float acc = bo;
#pragma unroll
        for (int k = 0; k < 32; k++) acc += irs[gg][k] * Ws[k][o];
        d_Sh[(size_t)(g0 + gg) * 128 + o] = __float2half_rn(fmaxf(acc, 0.f));
    }
}

// ---------------- stage D: persistent decode GEMM, 2 CTAs/SM (fp16 m16n8k16) --
// Z[8192,200] = A[8192,16384] @ W1, A[g, i*128+j] = P[g,i]*S[g,j].
// Grid = 2*NSM. CTA c: h = c&1 selects N-half (cols h*104..h*104+103),
// c2 = c>>1 selects unit range [c2*8192/NC2, ...) over (M-block, K-chunk).
// 2 CTAs/SM -> 4 warps/SMSP to cover LDS->HMMA latency.
// Partials: slot = c2&3; h-halves write disjoint columns of the same slot.
#define NSTB 4
#define BROW 48                        // padded B row stride (bytes)
#define BSTG (104 * BROW)              // 4992 B per stage
#define SM_B 0
#define SM_S (NSTB * BSTG)             // 19968; S: 128 rows x 304B = 38912
#define SM_P (SM_S + 128 * 304)        // 58880; P: 128 rows x 264B = 33792
#define SM_TOTAL (SM_P + 128 * 264)    // 92672

__global__ void __launch_bounds__(256, 2)
k_decode() {
    extern __shared__ char smem[];
    uint32_t sb = su32(smem);
    int tid = threadIdx.x;
    int lane = tid & 31, warp = tid >> 5;
    int wm = warp & 3, wn = warp >> 2;
    int gq = lane >> 2, l4 = lane & 3;
    int m_base = wm * 32;
    int c = blockIdx.x;
    int h = c & 1, c2 = c >> 1, NC2 = gridDim.x >> 1;
    int u0 = (c2 * NUNITS) / NC2;
    int u1 = ((c2 + 1) * NUNITS) / NC2;
    int T = (u1 - u0) * 8;
    int m = u0 >> 7;

    // ---- tile loaders
    auto load_tiles = [&](int mb) {
        int g0 = mb * 128;
        // S: rows g (stride 304B), 128 halfs = 256B each
        for (int l = tid; l < 2048; l += 256) {
            int row = l >> 4, cc = l & 15;
            *(float4*)(smem + SM_S + row * 304 + cc * 16) =
                *(const float4*)((const char*)d_Sh + (size_t)(g0 + row) * 256 + cc * 16);
        }
        // P: rows g (stride 264B), 128 halfs: P[g][i] = Hh[2(g0+g)+(i>=64)][i&63]
        for (int l = tid; l < 4096; l += 256) {
            int row = l >> 5, grp = l & 31;          // grp: 4-half (8B) group
            *(float2*)(smem + SM_P + row * 264 + grp * 8) =
                *(const float2*)((const char*)d_Hh +
                    ((size_t)(2 * (g0 + row) + (grp >> 4)) * 64 + (grp & 15) * 4) * 2);
        }
    };
    // ---- B stage loader (cp.async); this CTA's 104 N-rows only
    auto load_stage = [&](int buf, int t) {
        int iu = (u0 + (t >> 3)) & 127;
        int kb = iu * 128 + (t & 7) * 16;
        for (int l = tid; l < 208; l += 256) {
            int row = l >> 1, hh = l & 1;
            uint32_t dst = sb + SM_B + buf * BSTG + row * BROW + hh * 16;
            const char* src = (const char*)(d_W1h + (size_t)(h * 104 + row) * 16384 + kb + hh * 8);
            asm volatile("cp.async.cg.shared.global [%0], [%1], 16;\n"
                         :: "r"(dst), "l"(src));
        }
        asm volatile("cp.async.commit_group;\n");
    };

    float acc[2][7][4];
#pragma unroll
    for (int a = 0; a < 2; a++)
#pragma unroll
        for (int b = 0; b < 7; b++)
#pragma unroll
            for (int q = 0; q < 4; q++) acc[a][b][q] = 0.f;

    auto flush = [&](int mb) {
        int slot = c2 & 3;
        int base_col = h * 104;
#pragma unroll
        for (int mt = 0; mt < 2; mt++) {
            int gr = mb * 128 + m_base + mt * 16 + gq;
            size_t b0 = ((size_t)slot * GG + gr) * 208;
            size_t b1 = ((size_t)slot * GG + gr + 8) * 208;
            if (wn == 0) {
#pragma unroll
                for (int j = 0; j < 7; j++) {
                    int c0 = base_col + j * 8 + 2 * l4;
                    *(float2*)&d_Zp[b0 + c0] = make_float2(acc[mt][j][0], acc[mt][j][1]);
                    *(float2*)&d_Zp[b1 + c0] = make_float2(acc[mt][j][2], acc[mt][j][3]);
                }
            } else {
#pragma unroll
                for (int j = 0; j < 5; j++) {
                    int c0 = base_col + 56 + j * 8 + 2 * l4;
                    *(float2*)&d_Zp[b0 + c0] = make_float2(acc[mt][j][0], acc[mt][j][1]);
                    *(float2*)&d_Zp[b1 + c0] = make_float2(acc[mt][j][2], acc[mt][j][3]);
                }
                if (h == 0) {
                    int c0 = 96 + 2 * l4;
                    *(float2*)&d_Zp[b0 + c0] = make_float2(acc[mt][5][0], acc[mt][5][1]);
                    *(float2*)&d_Zp[b1 + c0] = make_float2(acc[mt][5][2], acc[mt][5][3]);
                }
            }
        }
#pragma unroll
        for (int a = 0; a < 2; a++)
#pragma unroll
            for (int b = 0; b < 7; b++)
#pragma unroll
                for (int q = 0; q < 4; q++) acc[a][b][q] = 0.f;
    };

    load_tiles(m);
    __syncthreads();
    load_stage(0, 0); load_stage(1, 1); load_stage(2, 2);

    __half2 pb[4];
    const int s_cb = (2 * l4) * 2;       // byte offset of j0 within S row

    for (int t = 0; t < T; t++) {
        int u = u0 + (t >> 3);
        int mblk = u >> 7;
        if (mblk != m) {
            flush(m);                    // registers -> global; smem untouched
            __syncthreads();             // all warps done reading old tiles
            load_tiles(mblk);
            __syncthreads();
            m = mblk;
        }
        asm volatile("cp.async.wait_group 2;\n" ::: "memory");
        __syncthreads();
        if (t + 3 < T) load_stage((t + 3) & 3, t + 3);
        else asm volatile("cp.async.commit_group;\n");

        int sub = t & 7;
        if (sub == 0) {
            int iu = u & 127;
#pragma unroll
            for (int t4 = 0; t4 < 4; t4++) {
                __half ph = *(const __half*)(smem + SM_P + (m_base + gq + 8 * t4) * 264 + iu * 2);
                pb[t4] = __half2half2(ph);
            }
        }
        int jb = sub * 16;
        // A fragments (depend on K only -> same for both N-halves)
        uint32_t afr[2][4];
#pragma unroll
        for (int mt = 0; mt < 2; mt++) {
            const char* r0p = smem + SM_S + (m_base + mt * 16 + gq) * 304 + jb * 2 + s_cb;
            const char* r1p = r0p + 8 * 304;
            __half2 s00 = *(const __half2*)(r0p);
            __half2 s10 = *(const __half2*)(r1p);
            __half2 s01 = *(const __half2*)(r0p + 16);
            __half2 s11 = *(const __half2*)(r1p + 16);
            __half2 a0 = __hmul2(pb[mt * 2],     s00);
            __half2 a1 = __hmul2(pb[mt * 2 + 1], s10);
            __half2 a2 = __hmul2(pb[mt * 2],     s01);
            __half2 a3 = __hmul2(pb[mt * 2 + 1], s11);
            afr[mt][0] = *(uint32_t*)&a0; afr[mt][1] = *(uint32_t*)&a1;
            afr[mt][2] = *(uint32_t*)&a2; afr[mt][3] = *(uint32_t*)&a3;
        }
        const char* bst = smem + SM_B + (t & 3) * BSTG;

#define MMA_TILE(jj, tl)                                                        \
        {                                                                       \
            const char* brow = bst + ((tl) * 8 + gq) * BROW + l4 * 4;           \
            uint32_t b0 = *(const uint32_t*)(brow);                             \
            uint32_t b1 = *(const uint32_t*)(brow + 16);                        \
            _Pragma("unroll")                                                   \
            for (int mt = 0; mt < 2; mt++) {                                    \
                asm volatile(                                                   \
                    "mma.sync.aligned.m16n8k16.row.col.f32.f16.f16.f32 "        \
                    "{%0,%1,%2,%3}, {%4,%5,%6,%7}, {%8,%9}, {%0,%1,%2,%3};"     \
                    : "+f"(acc[mt][jj][0]), "+f"(acc[mt][jj][1]),               \
                      "+f"(acc[mt][jj][2]), "+f"(acc[mt][jj][3])                \
                    : "r"(afr[mt][0]), "r"(afr[mt][1]),                         \
                      "r"(afr[mt][2]), "r"(afr[mt][3]),                         \
                      "r"(b0), "r"(b1));                                        \
            }                                                                   \
        }

        if (wn == 0) {
#pragma unroll
            for (int j = 0; j < 7; j++) MMA_TILE(j, j)
        } else {
#pragma unroll
            for (int j = 0; j < 5; j++) MMA_TILE(j, 7 + j)
            if (h == 0) MMA_TILE(5, 12)
        }
#undef MMA_TILE
    }

    flush(m);
}

// ---------------- epilogue: sum 4 partial slots, bias+relu, @W2 ----------------
__global__ void k_final(const float* __restrict__ b1, const float* __restrict__ W2,
                        const float* __restrict__ b2, float* __restrict__ out) {
    int g = (blockIdx.x * blockDim.x + threadIdx.x) >> 5;
    int lane = threadIdx.x & 31;
    if (g >= GG) return;
    float a0 = 0.f, a1 = 0.f;
    for (int n = lane; n < NOUT; n += 32) {
        float v = b1[n];
#pragma unroll
        for (int zz = 0; zz < NSLOTS_ZP; zz++) v += d_Zp[((size_t)zz * GG + g) * 208 + n];
        v = fmaxf(v, 0.f);
        a0 += v * W2[n * 2];
        a1 += v * W2[n * 2 + 1];
    }
#pragma unroll
    for (int o = 16; o; o >>= 1) {
        a0 += __shfl_down_sync(0xffffffffu, a0, o);
        a1 += __shfl_down_sync(0xffffffffu, a1, o);
    }
    if (lane == 0) { out[g * 2] = a0 + b2[0]; out[g * 2 + 1] = a1 + b2[1]; }
}

// ---------------- host ----------------
extern "C" void kernel_launch(void* const* d_in, const int* in_sizes, int n_in,
                              void* d_out, int out_size) {
    const float* x       = (const float*)d_in[0];
    const int*   ei      = (const int*)d_in[1];
    const int*   set_idx = (const int*)d_in[2];
    const float* ir      = (const float*)d_in[4];
    const float* Wl      = (const float*)d_in[5];
    const float* bl      = (const float*)d_in[6];
    const float* Wr      = (const float*)d_in[7];
    const float* Wir     = (const float*)d_in[8];
    const float* bir     = (const float*)d_in[9];
    const float* W1      = (const float*)d_in[10];
    const float* b1      = (const float*)d_in[11];
    const float* W2      = (const float*)d_in[12];
    const float* b2      = (const float*)d_in[13];
    float* out = (float*)d_out;

    // one-time host-side setup (streams/events are host resources, no dev mem)
    static cudaStream_t s1 = nullptr, s2 = nullptr;
    static cudaEvent_t ef = nullptr, e1 = nullptr, e2 = nullptr;
    static int nsm = 0;
    if (!s1) {
        cudaStreamCreateWithFlags(&s1, cudaStreamNonBlocking);
        cudaStreamCreateWithFlags(&s2, cudaStreamNonBlocking);
        cudaEventCreateWithFlags(&ef, cudaEventDisableTiming);
        cudaEventCreateWithFlags(&e1, cudaEventDisableTiming);
        cudaEventCreateWithFlags(&e2, cudaEventDisableTiming);
        cudaFuncSetAttribute(k_decode, cudaFuncAttributeMaxDynamicSharedMemorySize, SM_TOTAL);
        cudaDeviceGetAttribute(&nsm, cudaDevAttrMultiProcessorCount, 0);
        if (nsm < 4) nsm = 4;
    }

    void *p_mark, *p_cnt, *p_zp;
    cudaGetSymbolAddress(&p_mark, d_mark);
    cudaGetSymbolAddress(&p_cnt,  d_cnt);
    cudaGetSymbolAddress(&p_zp,   d_Zp);
    cudaMemsetAsync(p_mark, 0xFF, (size_t)NN * 4, 0);
    cudaMemsetAsync(p_cnt,  0,    (size_t)NSLOT * 4, 0);

    // fork: independent stages on side streams
    cudaEventRecord(ef, 0);
    cudaStreamWaitEvent(s1, ef, 0);
    cudaStreamWaitEvent(s2, ef, 0);
    cudaMemsetAsync(p_zp, 0, (size_t)NSLOTS_ZP * GG * 208 * 4, s1);
    k_prep<<<dim3(512, 7), dim3(32, 8), 0, s1>>>(W1);
    k_sgemm<<<GG / 64, 256, 0, s2>>>(ir, Wir, bir);

    // main chain on origin stream
    k_mark<<<NSLOT / 256, 256>>>(set_idx);
    k_fill<<<EE / 2048, 256>>>(ei);
    k_agg<<<NSLOT / 8, 256>>>(x);
    k_fix<<<NSLOT / 8, 256>>>();
    k_hgemm<<<NSLOT / 128, 256>>>(Wl, Wr, bl);

    // join
    cudaEventRecord(e1, s1);
    cudaEventRecord(e2, s2);
    cudaStreamWaitEvent(0, e1, 0);
    cudaStreamWaitEvent(0, e2, 0);

    k_decode<<<2 * nsm, 256, SM_TOTAL>>>();
    k_final<<<(GG * 32 + 255) / 256, 256>>>(b1, W2, b2, out);
}

// round 13
// speedup vs baseline: 2.1804x; 1.1509x over previous
#include <cuda_runtime.h>
#include <cuda_fp16.h>
#include <cstdint>

// ---------------- problem constants (fixed shapes) ----------------
#define NN     131072      // nodes
#define EE     2097152     // edges
#define GG     8192        // graphs
#define NPG    16
#define NSLOT  16384       // 2 per graph
#define GS     64
#define NOUT   200
#define NSLOTS_ZP 4        // partial slots for decode
#define ECAP   64          // per-slot edge bucket capacity
#define NUNITS 8192        // 64 M-blocks x 128 K-chunks

// ---------------- scratch (device globals; no runtime alloc) ----------------
__device__ int      d_mark[NN];
__device__ uint32_t d_bits[NN / 32];          // 16KB membership bitmask (L1-resident)
__device__ int      d_node_of[NSLOT];
__device__ int      d_cnt[NSLOT];
__device__ int      d_elist[NSLOT * ECAP];    // [slot][ECAP]
__device__ float    d_MX[NSLOT * 256];        // [slot][mean(128) | xv(128)]
__device__ __half   d_Hh[NSLOT * GS];         // h per slot (fp16)
__device__ __half   d_Sh[GG * 128];           // fused ir features (fp16)
__device__ __half   d_W1h[208 * 16384];       // W1 transposed (n-major), fp16, zero-padded
__device__ float    d_Zp[(size_t)NSLOTS_ZP * GG * 208]; // decode partials (4 slots)

__device__ __forceinline__ uint32_t su32(const void* p) {
    return (uint32_t)__cvta_generic_to_shared(p);
}

// ---------------- stage 0: W1 transpose + fp16 round ----------------
__global__ void k_prep(const float* __restrict__ W1) {
    __shared__ float tile[32][33];
    int kb = blockIdx.x * 32, nb = blockIdx.y * 32;
    int tx = threadIdx.x, ty = threadIdx.y;
#pragma unroll
    for (int r = 0; r < 4; r++) {
        int k = kb + ty + r * 8;
        int n = nb + tx;
        tile[ty + r * 8][tx] = (n < NOUT) ? W1[(size_t)k * NOUT + n] : 0.f;
    }
    __syncthreads();
#pragma unroll
    for (int r = 0; r < 4; r++) {
        int n = nb + ty + r * 8;
        if (n < 208) d_W1h[(size_t)n * 16384 + kb + tx] = __float2half_rn(tile[tx][ty + r * 8]);
    }
}

// ---------------- stage A: mark / bucket-fill / aggregate ----------------
__global__ void k_mark(const int* __restrict__ set_idx) {
    int s = blockIdx.x * blockDim.x + threadIdx.x;
    if (s >= NSLOT) return;
    int g = s >> 1, k = s & 1;
    int v = g * NPG + set_idx[g * 2 + k];
    d_node_of[s] = v;
    atomicMax(&d_mark[v], s);
    atomicOr(&d_bits[v >> 5], 1u << (v & 31));
}

// bucketed edge fill; 8 edges/thread; L1-resident bitmask pre-filter
__global__ void k_fill(const int* __restrict__ ei) {
    int e0 = (blockIdx.x * blockDim.x + threadIdx.x) * 8;
    if (e0 >= EE) return;
    int4 a = *(const int4*)&ei[EE + e0];
    int4 b = *(const int4*)&ei[EE + e0 + 4];
    int v[8] = {a.x, a.y, a.z, a.w, b.x, b.y, b.z, b.w};
    uint32_t hit = 0;
#pragma unroll
    for (int q = 0; q < 8; q++)
        hit |= ((d_bits[v[q] >> 5] >> (v[q] & 31)) & 1u) << q;
    if (!hit) return;
#pragma unroll
    for (int q = 0; q < 8; q++) {
        if (hit & (1u << q)) {
            int r = d_mark[v[q]];
            int p = atomicAdd(&d_cnt[r], 1);
            if (p < ECAP) d_elist[r * ECAP + p] = ei[e0 + q];
        }
    }
}

// aggregate: every slot reads its representative's bucket (no fix pass needed)
__global__ void k_agg(const float* __restrict__ x) {
    int s = blockIdx.x * 8 + (threadIdx.x >> 5);
    int lane = threadIdx.x & 31;
    int v = d_node_of[s];
    int rep = d_mark[v];                         // bucket key (== s unless dup)
    const float4* x4 = (const float4*)x;
    const int* el = &d_elist[rep * ECAP];
    int deg = d_cnt[rep];
    int n = deg > ECAP ? ECAP : deg;
    float4 acc = make_float4(0.f, 0.f, 0.f, 0.f);
    int i = 0;
    for (; i + 4 <= n; i += 4) {
        int s0 = el[i], s1 = el[i + 1], s2 = el[i + 2], s3 = el[i + 3];
        float4 t0 = x4[(size_t)s0 * 32 + lane];
        float4 t1 = x4[(size_t)s1 * 32 + lane];
        float4 t2 = x4[(size_t)s2 * 32 + lane];
        float4 t3 = x4[(size_t)s3 * 32 + lane];
        acc.x += (t0.x + t1.x) + (t2.x + t3.x);
        acc.y += (t0.y + t1.y) + (t2.y + t3.y);
        acc.z += (t0.z + t1.z) + (t2.z + t3.z);
        acc.w += (t0.w + t1.w) + (t2.w + t3.w);
    }
    for (; i < n; i++) {
        float4 t = x4[(size_t)el[i] * 32 + lane];
        acc.x += t.x; acc.y += t.y; acc.z += t.z; acc.w += t.w;
    }
    float inv = 1.f / (float)(deg > 0 ? deg : 1);
    acc.x *= inv; acc.y *= inv; acc.z *= inv; acc.w *= inv;
    float4* MX4 = (float4*)d_MX;
    MX4[(size_t)s * 64 + lane]      = acc;
    MX4[(size_t)s * 64 + 32 + lane] = x4[(size_t)v * 32 + lane];
}

// ---------------- stage B: H = relu(MX @ [Wl;Wr] + bl) -> fp16 ----------------
__global__ void k_hgemm(const float* __restrict__ Wl, const float* __restrict__ Wr,
                        const float* __restrict__ bl) {
    __shared__ float As[16][132];   // [k][row], transposed
    __shared__ float Bs[16][64];
    int tid = threadIdx.x;
    int tx = tid & 15, ty = tid >> 4;
    int row0 = blockIdx.x * 128;
    float acc[8][4];
#pragma unroll
    for (int i = 0; i < 8; i++)
#pragma unroll
        for (int j = 0; j < 4; j++) acc[i][j] = 0.f;

    for (int kb = 0; kb < 256; kb += 16) {
        for (int l = tid; l < 512; l += 256) {
            int r = l >> 2, q = l & 3;
            float4 v = *(const float4*)&d_MX[(size_t)(row0 + r) * 256 + kb + q * 4];
            As[q * 4 + 0][r] = v.x; As[q * 4 + 1][r] = v.y;
            As[q * 4 + 2][r] = v.z; As[q * 4 + 3][r] = v.w;
        }
        {
            int k = tid >> 4, o4 = (tid & 15) * 4;
            int kg = kb + k;
            const float* Wsrc = (kg < 128) ? &Wl[kg * 64 + o4] : &Wr[(kg - 128) * 64 + o4];
            *(float4*)&Bs[k][o4] = *(const float4*)Wsrc;
        }
        __syncthreads();
#pragma unroll
        for (int k = 0; k < 16; k++) {
            float a[8], b[4];
#pragma unroll
            for (int i = 0; i < 8; i++) a[i] = As[k][ty * 8 + i];
#pragma unroll
            for (int j = 0; j < 4; j++) b[j] = Bs[k][tx * 4 + j];
#pragma unroll
            for (int i = 0; i < 8; i++)
#pragma unroll
                for (int j = 0; j < 4; j++) acc[i][j] += a[i] * b[j];
        }
        __syncthreads();
    }
#pragma unroll
    for (int i = 0; i < 8; i++)
#pragma unroll
        for (int j = 0; j < 4; j++) {
            int o = tx * 4 + j;
            d_Hh[(size_t)(row0 + ty * 8 + i) * 64 + o] =
                __float2half_rn(fmaxf(acc[i][j] + bl[o], 0.f));
        }
}

// ---------------- stage C: S = relu(ir @ Wir + bir) -> fp16 ----------------
__global__ void k_sgemm(const float* __restrict__ ir, const float* __restrict__ Wir,
                        const float* __restrict__ bir) {
    __shared__ float irs[64][32];
    __shared__ float Ws[32][128];
    int tid = threadIdx.x;
    int g0 = blockIdx.x * 64;
    for (int l = tid; l < 64 * 32; l += 256) irs[l >> 5][l & 31] = ir[(size_t)g0 * 32 + l];
    for (int l = tid; l < 32 * 128; l += 256) Ws[l >> 7][l & 127] = Wir[l];
    __syncthreads();
    int o = tid & 127, h = tid >> 7;
    float bo = bir[o];
    for (int gg = h; gg < 64; gg += 2) {
        float acc = bo;
#pragma unroll
        for (int k = 0; k < 32; k++) acc += irs[gg][k] * Ws[k][o];
        d_Sh[(size_t)(g0 + gg) * 128 + o] = __float2half_rn(fmaxf(acc, 0.f));
    }
}

// ---------------- stage D: persistent decode GEMM, 2 CTAs/SM, k32 stages ------
// Z[8192,200] = A[8192,16384] @ W1, A[g, i*128+j] = P[g,i]*S[g,j].
// Grid = 2*NSM. CTA c: h = c&1 selects N-half, c2 = c>>1 selects unit range.
// Stage = k32 (two k16 sub-steps per sync) -> half the barrier/cp.async overhead.
#define NSTB 4
#define BROW 80                        // 64B data + 16B pad (conflict-free)
#define BSTG (104 * BROW)              // 8320 B per stage
#define SM_B 0
#define SM_S (NSTB * BSTG)             // 33280; S: 128 rows x 304B = 38912
#define SM_P (SM_S + 128 * 304)        // 72192; P: 128 rows x 264B = 33792
#define SM_TOTAL (SM_P + 128 * 264)    // 105984

__global__ void __launch_bounds__(256, 2)
k_decode() {
    extern __shared__ char smem[];
    uint32_t sb = su32(smem);
    int tid = threadIdx.x;
    int lane = tid & 31, warp = tid >> 5;
    int wm = warp & 3, wn = warp >> 2;
    int gq = lane >> 2, l4 = lane & 3;
    int m_base = wm * 32;
    int c = blockIdx.x;
    int h = c & 1, c2 = c >> 1, NC2 = gridDim.x >> 1;
    int u0 = (c2 * NUNITS) / NC2;
    int u1 = ((c2 + 1) * NUNITS) / NC2;
    int T = (u1 - u0) * 4;             // k32 stages
    int m = u0 >> 7;

    // ---- tile loaders
    auto load_tiles = [&](int mb) {
        int g0 = mb * 128;
        for (int l = tid; l < 2048; l += 256) {
            int row = l >> 4, cc = l & 15;
            *(float4*)(smem + SM_S + row * 304 + cc * 16) =
                *(const float4*)((const char*)d_Sh + (size_t)(g0 + row) * 256 + cc * 16);
        }
        for (int l = tid; l < 4096; l += 256) {
            int row = l >> 5, grp = l & 31;
            *(float2*)(smem + SM_P + row * 264 + grp * 8) =
                *(const float2*)((const char*)d_Hh +
                    ((size_t)(2 * (g0 + row) + (grp >> 4)) * 64 + (grp & 15) * 4) * 2);
        }
    };
    // ---- B stage loader (cp.async): 104 rows x 64B (k32)
    auto load_stage = [&](int buf, int t) {
        int iu = (u0 + (t >> 2)) & 127;
        int kb = iu * 128 + (t & 3) * 32;
        for (int l = tid; l < 416; l += 256) {
            int row = l >> 2, q = l & 3;
            uint32_t dst = sb + SM_B + buf * BSTG + row * BROW + q * 16;
            const char* src = (const char*)(d_W1h + (size_t)(h * 104 + row) * 16384 + kb + q * 8);
            asm volatile("cp.async.cg.shared.global [%0], [%1], 16;\n"
                         :: "r"(dst), "l"(src));
        }
        asm volatile("cp.async.commit_group;\n");
    };

    float acc[2][7][4];
#pragma unroll
    for (int a = 0; a < 2; a++)
#pragma unroll
        for (int b = 0; b < 7; b++)
#pragma unroll
            for (int q = 0; q < 4; q++) acc[a][b][q] = 0.f;

    auto flush = [&](int mb) {
        int slot = c2 & 3;
        int base_col = h * 104;
#pragma unroll
        for (int mt = 0; mt < 2; mt++) {
            int gr = mb * 128 + m_base + mt * 16 + gq;
            size_t b0 = ((size_t)slot * GG + gr) * 208;
            size_t b1 = ((size_t)slot * GG + gr + 8) * 208;
            if (wn == 0) {
#pragma unroll
                for (int j = 0; j < 7; j++) {
                    int c0 = base_col + j * 8 + 2 * l4;
                    *(float2*)&d_Zp[b0 + c0] = make_float2(acc[mt][j][0], acc[mt][j][1]);
                    *(float2*)&d_Zp[b1 + c0] = make_float2(acc[mt][j][2], acc[mt][j][3]);
                }
            } else {
#pragma unroll
                for (int j = 0; j < 5; j++) {
                    int c0 = base_col + 56 + j * 8 + 2 * l4;
                    *(float2*)&d_Zp[b0 + c0] = make_float2(acc[mt][j][0], acc[mt][j][1]);
                    *(float2*)&d_Zp[b1 + c0] = make_float2(acc[mt][j][2], acc[mt][j][3]);
                }
                if (h == 0) {
                    int c0 = 96 + 2 * l4;
                    *(float2*)&d_Zp[b0 + c0] = make_float2(acc[mt][5][0], acc[mt][5][1]);
                    *(float2*)&d_Zp[b1 + c0] = make_float2(acc[mt][5][2], acc[mt][5][3]);
                }
            }
        }
#pragma unroll
        for (int a = 0; a < 2; a++)
#pragma unroll
            for (int b = 0; b < 7; b++)
#pragma unroll
                for (int q = 0; q < 4; q++) acc[a][b][q] = 0.f;
    };

    load_tiles(m);
    __syncthreads();
    load_stage(0, 0); load_stage(1, 1); load_stage(2, 2);

    __half2 pb[4];
    const int s_cb = (2 * l4) * 2;       // byte offset of j0 within S row

    for (int t = 0; t < T; t++) {
        int u = u0 + (t >> 2);
        int mblk = u >> 7;
        if (mblk != m) {
            flush(m);
            __syncthreads();
            load_tiles(mblk);
            __syncthreads();
            m = mblk;
        }
        asm volatile("cp.async.wait_group 2;\n" ::: "memory");
        __syncthreads();
        if (t + 3 < T) load_stage((t + 3) & 3, t + 3);
        else asm volatile("cp.async.commit_group;\n");

        if ((t & 3) == 0) {
            int iu = u & 127;
#pragma unroll
            for (int t4 = 0; t4 < 4; t4++) {
                __half ph = *(const __half*)(smem + SM_P + (m_base + gq + 8 * t4) * 264 + iu * 2);
                pb[t4] = __half2half2(ph);
            }
        }
        const char* bst = smem + SM_B + (t & 3) * BSTG;

#pragma unroll
        for (int ss = 0; ss < 2; ss++) {
            int jb = (t & 3) * 32 + ss * 16;
            // A fragments (K-only -> same for both N-halves)
            uint32_t afr[2][4];
#pragma unroll
            for (int mt = 0; mt < 2; mt++) {
                const char* r0p = smem + SM_S + (m_base + mt * 16 + gq) * 304 + jb * 2 + s_cb;
                const char* r1p = r0p + 8 * 304;
                __half2 s00 = *(const __half2*)(r0p);
                __half2 s10 = *(const __half2*)(r1p);
                __half2 s01 = *(const __half2*)(r0p + 16);
                __half2 s11 = *(const __half2*)(r1p + 16);
                __half2 a0 = __hmul2(pb[mt * 2],     s00);
                __half2 a1 = __hmul2(pb[mt * 2 + 1], s10);
                __half2 a2 = __hmul2(pb[mt * 2],     s01);
                __half2 a3 = __hmul2(pb[mt * 2 + 1], s11);
                afr[mt][0] = *(uint32_t*)&a0; afr[mt][1] = *(uint32_t*)&a1;
                afr[mt][2] = *(uint32_t*)&a2; afr[mt][3] = *(uint32_t*)&a3;
            }

#define MMA_TILE(jj, tl)                                                        \
            {                                                                   \
                const char* brow = bst + ((tl) * 8 + gq) * BROW + ss * 32 + l4 * 4; \
                uint32_t b0 = *(const uint32_t*)(brow);                         \
                uint32_t b1 = *(const uint32_t*)(brow + 16);                    \
                _Pragma("unroll")                                               \
                for (int mt = 0; mt < 2; mt++) {                                \
                    asm volatile(                                               \
                        "mma.sync.aligned.m16n8k16.row.col.f32.f16.f16.f32 "    \
                        "{%0,%1,%2,%3}, {%4,%5,%6,%7}, {%8,%9}, {%0,%1,%2,%3};" \
                        : "+f"(acc[mt][jj][0]), "+f"(acc[mt][jj][1]),           \
                          "+f"(acc[mt][jj][2]), "+f"(acc[mt][jj][3])            \
                        : "r"(afr[mt][0]), "r"(afr[mt][1]),                     \
                          "r"(afr[mt][2]), "r"(afr[mt][3]),                     \
                          "r"(b0), "r"(b1));                                    \
                }                                                               \
            }

            if (wn == 0) {
#pragma unroll
                for (int j = 0; j < 7; j++) MMA_TILE(j, j)
            } else {
#pragma unroll
                for (int j = 0; j < 5; j++) MMA_TILE(j, 7 + j)
                if (h == 0) MMA_TILE(5, 12)
            }
#undef MMA_TILE
        }
    }

    flush(m);
}

// ---------------- epilogue: sum 4 partial slots, bias+relu, @W2 ----------------
__global__ void k_final(const float* __restrict__ b1, const float* __restrict__ W2,
                        const float* __restrict__ b2, float* __restrict__ out) {
    int g = (blockIdx.x * blockDim.x + threadIdx.x) >> 5;
    int lane = threadIdx.x & 31;
    if (g >= GG) return;
    float a0 = 0.f, a1 = 0.f;
    for (int n = lane; n < NOUT; n += 32) {
        float v = b1[n];
#pragma unroll
        for (int zz = 0; zz < NSLOTS_ZP; zz++) v += d_Zp[((size_t)zz * GG + g) * 208 + n];
        v = fmaxf(v, 0.f);
        a0 += v * W2[n * 2];
        a1 += v * W2[n * 2 + 1];
    }
#pragma unroll
    for (int o = 16; o; o >>= 1) {
        a0 += __shfl_down_sync(0xffffffffu, a0, o);
        a1 += __shfl_down_sync(0xffffffffu, a1, o);
    }
    if (lane == 0) { out[g * 2] = a0 + b2[0]; out[g * 2 + 1] = a1 + b2[1]; }
}

// ---------------- host ----------------
extern "C" void kernel_launch(void* const* d_in, const int* in_sizes, int n_in,
                              void* d_out, int out_size) {
    const float* x       = (const float*)d_in[0];
    const int*   ei      = (const int*)d_in[1];
    const int*   set_idx = (const int*)d_in[2];
    const float* ir      = (const float*)d_in[4];
    const float* Wl      = (const float*)d_in[5];
    const float* bl      = (const float*)d_in[6];
    const float* Wr      = (const float*)d_in[7];
    const float* Wir     = (const float*)d_in[8];
    const float* bir     = (const float*)d_in[9];
    const float* W1      = (const float*)d_in[10];
    const float* b1      = (const float*)d_in[11];
    const float* W2      = (const float*)d_in[12];
    const float* b2      = (const float*)d_in[13];
    float* out = (float*)d_out;

    // one-time host-side setup (streams/events are host resources, no dev mem)
    static cudaStream_t s1 = nullptr, s2 = nullptr;
    static cudaEvent_t ef = nullptr, e1 = nullptr, e2 = nullptr;
    static int nsm = 0;
    if (!s1) {
        cudaStreamCreateWithFlags(&s1, cudaStreamNonBlocking);
        cudaStreamCreateWithFlags(&s2, cudaStreamNonBlocking);
        cudaEventCreateWithFlags(&ef, cudaEventDisableTiming);
        cudaEventCreateWithFlags(&e1, cudaEventDisableTiming);
        cudaEventCreateWithFlags(&e2, cudaEventDisableTiming);
        cudaFuncSetAttribute(k_decode, cudaFuncAttributeMaxDynamicSharedMemorySize, SM_TOTAL);
        cudaDeviceGetAttribute(&nsm, cudaDevAttrMultiProcessorCount, 0);
        if (nsm < 4) nsm = 4;
    }

    void *p_mark, *p_cnt, *p_zp, *p_bits;
    cudaGetSymbolAddress(&p_mark, d_mark);
    cudaGetSymbolAddress(&p_cnt,  d_cnt);
    cudaGetSymbolAddress(&p_zp,   d_Zp);
    cudaGetSymbolAddress(&p_bits, d_bits);
    cudaMemsetAsync(p_mark, 0xFF, (size_t)NN * 4, 0);
    cudaMemsetAsync(p_bits, 0,    (size_t)(NN / 32) * 4, 0);
    cudaMemsetAsync(p_cnt,  0,    (size_t)NSLOT * 4, 0);

    // fork: independent stages on side streams
    cudaEventRecord(ef, 0);
    cudaStreamWaitEvent(s1, ef, 0);
    cudaStreamWaitEvent(s2, ef, 0);
    cudaMemsetAsync(p_zp, 0, (size_t)NSLOTS_ZP * GG * 208 * 4, s1);
    k_prep<<<dim3(512, 7), dim3(32, 8), 0, s1>>>(W1);
    k_sgemm<<<GG / 64, 256, 0, s2>>>(ir, Wir, bir);

    // main chain on origin stream
    k_mark<<<NSLOT / 256, 256>>>(set_idx);
    k_fill<<<EE / 2048, 256>>>(ei);
    k_agg<<<NSLOT / 8, 256>>>(x);
    k_hgemm<<<NSLOT / 128, 256>>>(Wl, Wr, bl);

    // join
    cudaEventRecord(e1, s1);
    cudaEventRecord(e2, s2);
    cudaStreamWaitEvent(0, e1, 0);
    cudaStreamWaitEvent(0, e2, 0);

    k_decode<<<2 * nsm, 256, SM_TOTAL>>>();
    k_final<<<(GG * 32 + 255) / 256, 256>>>(b1, W2, b2, out);
}

// round 14
// speedup vs baseline: 2.3634x; 1.0839x over previous
#include <cuda_runtime.h>
#include <cuda_fp16.h>
#include <cstdint>

// ---------------- problem constants (fixed shapes) ----------------
#define NN     131072      // nodes
#define EE     2097152     // edges
#define GG     8192        // graphs
#define NPG    16
#define NSLOT  16384       // 2 per graph
#define GS     64
#define NOUT   200
#define NSLOTS_ZP 4        // partial slots for decode
#define ECAP   64          // per-slot edge bucket capacity
#define NUNITS 8192        // 64 M-blocks x 128 K-chunks

// ---------------- scratch (device globals; no runtime alloc) ----------------
__device__ int      d_mark[NN];
__device__ uint32_t d_bits[NN / 32];          // 16KB membership bitmask (L1-resident)
__device__ int      d_node_of[NSLOT];
__device__ int      d_cnt[NSLOT];
__device__ int      d_elist[NSLOT * ECAP];    // [slot][ECAP]
__device__ float    d_MX[NSLOT * 256];        // [slot][mean(128) | xv(128)]
__device__ __half   d_Hh[NSLOT * GS];         // h per slot (fp16)
__device__ __half   d_Sh[GG * 128];           // fused ir features (fp16)
__device__ __half   d_W1h[208 * 16384];       // W1 transposed (n-major), fp16, zero-padded
__device__ float    d_Zp[(size_t)NSLOTS_ZP * GG * 208]; // decode partials (4 slots)

__device__ __forceinline__ uint32_t su32(const void* p) {
    return (uint32_t)__cvta_generic_to_shared(p);
}

// ---------------- stage 0: W1 transpose + fp16 round ----------------
__global__ void k_prep(const float* __restrict__ W1) {
    __shared__ float tile[32][33];
    int kb = blockIdx.x * 32, nb = blockIdx.y * 32;
    int tx = threadIdx.x, ty = threadIdx.y;
#pragma unroll
    for (int r = 0; r < 4; r++) {
        int k = kb + ty + r * 8;
        int n = nb + tx;
        tile[ty + r * 8][tx] = (n < NOUT) ? W1[(size_t)k * NOUT + n] : 0.f;
    }
    __syncthreads();
#pragma unroll
    for (int r = 0; r < 4; r++) {
        int n = nb + ty + r * 8;
        if (n < 208) d_W1h[(size_t)n * 16384 + kb + tx] = __float2half_rn(tile[tx][ty + r * 8]);
    }
}

// ---------------- stage A: mark / bucket-fill / aggregate ----------------
__global__ void k_mark(const int* __restrict__ set_idx) {
    int s = blockIdx.x * blockDim.x + threadIdx.x;
    if (s >= NSLOT) return;
    int g = s >> 1, k = s & 1;
    int v = g * NPG + set_idx[g * 2 + k];
    d_node_of[s] = v;
    atomicMax(&d_mark[v], s);
    atomicOr(&d_bits[v >> 5], 1u << (v & 31));
}

// bucketed edge fill; 8 edges/thread; L1-resident bitmask pre-filter
__global__ void k_fill(const int* __restrict__ ei) {
    int e0 = (blockIdx.x * blockDim.x + threadIdx.x) * 8;
    if (e0 >= EE) return;
    int4 a = *(const int4*)&ei[EE + e0];
    int4 b = *(const int4*)&ei[EE + e0 + 4];
    int v[8] = {a.x, a.y, a.z, a.w, b.x, b.y, b.z, b.w};
    uint32_t hit = 0;
#pragma unroll
    for (int q = 0; q < 8; q++)
        hit |= ((d_bits[v[q] >> 5] >> (v[q] & 31)) & 1u) << q;
    if (!hit) return;
#pragma unroll
    for (int q = 0; q < 8; q++) {
        if (hit & (1u << q)) {
            int r = d_mark[v[q]];
            int p = atomicAdd(&d_cnt[r], 1);
            if (p < ECAP) d_elist[r * ECAP + p] = ei[e0 + q];
        }
    }
}

// aggregate: every slot reads its representative's bucket (no fix pass needed)
__global__ void k_agg(const float* __restrict__ x) {
    int s = blockIdx.x * 8 + (threadIdx.x >> 5);
    int lane = threadIdx.x & 31;
    int v = d_node_of[s];
    int rep = d_mark[v];                         // bucket key (== s unless dup)
    const float4* x4 = (const float4*)x;
    const int* el = &d_elist[rep * ECAP];
    int deg = d_cnt[rep];
    int n = deg > ECAP ? ECAP : deg;
    float4 acc = make_float4(0.f, 0.f, 0.f, 0.f);
    int i = 0;
    for (; i + 4 <= n; i += 4) {
        int s0 = el[i], s1 = el[i + 1], s2 = el[i + 2], s3 = el[i + 3];
        float4 t0 = x4[(size_t)s0 * 32 + lane];
        float4 t1 = x4[(size_t)s1 * 32 + lane];
        float4 t2 = x4[(size_t)s2 * 32 + lane];
        float4 t3 = x4[(size_t)s3 * 32 + lane];
        acc.x += (t0.x + t1.x) + (t2.x + t3.x);
        acc.y += (t0.y + t1.y) + (t2.y + t3.y);
        acc.z += (t0.z + t1.z) + (t2.z + t3.z);
        acc.w += (t0.w + t1.w) + (t2.w + t3.w);
    }
    for (; i < n; i++) {
        float4 t = x4[(size_t)el[i] * 32 + lane];
        acc.x += t.x; acc.y += t.y; acc.z += t.z; acc.w += t.w;
    }
    float inv = 1.f / (float)(deg > 0 ? deg : 1);
    acc.x *= inv; acc.y *= inv; acc.z *= inv; acc.w *= inv;
    float4* MX4 = (float4*)d_MX;
    MX4[(size_t)s * 64 + lane]      = acc;
    MX4[(size_t)s * 64 + 32 + lane] = x4[(size_t)v * 32 + lane];
}

// ---------------- stage B: H = relu(MX @ [Wl;Wr] + bl) -> fp16 ----------------
__global__ void k_hgemm(const float* __restrict__ Wl, const float* __restrict__ Wr,
                        const float* __restrict__ bl) {
    __shared__ float As[16][132];   // [k][row], transposed
    __shared__ float Bs[16][64];
    int tid = threadIdx.x;
    int tx = tid & 15, ty = tid >> 4;
    int row0 = blockIdx.x * 128;
    float acc[8][4];
#pragma unroll
    for (int i = 0; i < 8; i++)
#pragma unroll
        for (int j = 0; j < 4; j++) acc[i][j] = 0.f;

    for (int kb = 0; kb < 256; kb += 16) {
        for (int l = tid; l < 512; l += 256) {
            int r = l >> 2, q = l & 3;
            float4 v = *(const float4*)&d_MX[(size_t)(row0 + r) * 256 + kb + q * 4];
            As[q * 4 + 0][r] = v.x; As[q * 4 + 1][r] = v.y;
            As[q * 4 + 2][r] = v.z; As[q * 4 + 3][r] = v.w;
        }
        {
            int k = tid >> 4, o4 = (tid & 15) * 4;
            int kg = kb + k;
            const float* Wsrc = (kg < 128) ? &Wl[kg * 64 + o4] : &Wr[(kg - 128) * 64 + o4];
            *(float4*)&Bs[k][o4] = *(const float4*)Wsrc;
        }
        __syncthreads();
#pragma unroll
        for (int k = 0; k < 16; k++) {
            float a[8], b[4];
#pragma unroll
            for (int i = 0; i < 8; i++) a[i] = As[k][ty * 8 + i];
#pragma unroll
            for (int j = 0; j < 4; j++) b[j] = Bs[k][tx * 4 + j];
#pragma unroll
            for (int i = 0; i < 8; i++)
#pragma unroll
                for (int j = 0; j < 4; j++) acc[i][j] += a[i] * b[j];
        }
        __syncthreads();
    }
#pragma unroll
    for (int i = 0; i < 8; i++)
#pragma unroll
        for (int j = 0; j < 4; j++) {
            int o = tx * 4 + j;
            d_Hh[(size_t)(row0 + ty * 8 + i) * 64 + o] =
                __float2half_rn(fmaxf(acc[i][j] + bl[o], 0.f));
        }
}

// ---------------- stage C: S = relu(ir @ Wir + bir) -> fp16 ----------------
__global__ void k_sgemm(const float* __restrict__ ir, const float* __restrict__ Wir,
                        const float* __restrict__ bir) {
    __shared__ float irs[64][32];
    __shared__ float Ws[32][128];
    int tid = threadIdx.x;
    int g0 = blockIdx.x * 64;
    for (int l = tid; l < 64 * 32; l += 256) irs[l >> 5][l & 31] = ir[(size_t)g0 * 32 + l];
    for (int l = tid; l < 32 * 128; l += 256) Ws[l >> 7][l & 127] = Wir[l];
    __syncthreads();
    int o = tid & 127, h = tid >> 7;
    float bo = bir[o];
    for (int gg = h; gg < 64; gg += 2) {
        float acc = bo;
#pragma unroll
        for (int k = 0; k < 32; k++) acc += irs[gg][k] * Ws[k][o];
        d_Sh[(size_t)(g0 + gg) * 128 + o] = __float2half_rn(fmaxf(acc, 0.f));
    }
}

// ---------------- stage D: persistent decode GEMM, 2 CTAs/SM, k64 stages ------
// Z[8192,200] = A[8192,16384] @ W1, A[g, i*128+j] = P[g,i]*S[g,j].
// Grid = 2*NSM. CTA c: h = c&1 selects N-half, c2 = c>>1 selects unit range.
// Stage = k64 (four k16 sub-steps per sync), 3-deep cp.async ring.
// B tiles depend only on k-index (not M-block) -> prefetch valid across M switch.
#define NSTB 3
#define BROW 144                       // 128B data + 16B pad (bank = 4*gq+l4, distinct)
#define BSTG (104 * BROW)              // 14976 B per stage
#define SM_B 0
#define SM_S (NSTB * BSTG)             // 44928; S: 128 rows x 272B = 34816
#define SM_P (SM_S + 128 * 272)        // 79744; P: 128 rows x 264B = 33792
#define SM_TOTAL (SM_P + 128 * 264)    // 113536

__global__ void __launch_bounds__(256, 2)
k_decode() {
    extern __shared__ char smem[];
    uint32_t sb = su32(smem);
    int tid = threadIdx.x;
    int lane = tid & 31, warp = tid >> 5;
    int wm = warp & 3, wn = warp >> 2;
    int gq = lane >> 2, l4 = lane & 3;
    int m_base = wm * 32;
    int c = blockIdx.x;
    int h = c & 1, c2 = c >> 1, NC2 = gridDim.x >> 1;
    int u0 = (c2 * NUNITS) / NC2;
    int u1 = ((c2 + 1) * NUNITS) / NC2;
    int T = (u1 - u0) * 2;             // k64 stages (2 per K-chunk of 128)
    int m = u0 >> 7;

    // ---- tile loaders
    auto load_tiles = [&](int mb) {
        int g0 = mb * 128;
        for (int l = tid; l < 2048; l += 256) {
            int row = l >> 4, cc = l & 15;
            *(float4*)(smem + SM_S + row * 272 + cc * 16) =
                *(const float4*)((const char*)d_Sh + (size_t)(g0 + row) * 256 + cc * 16);
        }
        for (int l = tid; l < 4096; l += 256) {
            int row = l >> 5, grp = l & 31;
            *(float2*)(smem + SM_P + row * 264 + grp * 8) =
                *(const float2*)((const char*)d_Hh +
                    ((size_t)(2 * (g0 + row) + (grp >> 4)) * 64 + (grp & 15) * 4) * 2);
        }
    };
    // ---- B stage loader (cp.async): 104 rows x 128B (k64)
    auto load_stage = [&](int buf, int t) {
        int iu = (u0 + (t >> 1)) & 127;
        int kb = iu * 128 + (t & 1) * 64;
        for (int l = tid; l < 832; l += 256) {
            int row = l >> 3, q = l & 7;
            uint32_t dst = sb + SM_B + buf * BSTG + row * BROW + q * 16;
            const char* src = (const char*)(d_W1h + (size_t)(h * 104 + row) * 16384 + kb + q * 8);
            asm volatile("cp.async.cg.shared.global [%0], [%1], 16;\n"
                         :: "r"(dst), "l"(src));
        }
        asm volatile("cp.async.commit_group;\n");
    };

    float acc[2][7][4];
#pragma unroll
    for (int a = 0; a < 2; a++)
#pragma unroll
        for (int b = 0; b < 7; b++)
#pragma unroll
            for (int q = 0; q < 4; q++) acc[a][b][q] = 0.f;

    auto flush = [&](int mb) {
        int slot = c2 & 3;
        int base_col = h * 104;
#pragma unroll
        for (int mt = 0; mt < 2; mt++) {
            int gr = mb * 128 + m_base + mt * 16 + gq;
            size_t b0 = ((size_t)slot * GG + gr) * 208;
            size_t b1 = ((size_t)slot * GG + gr + 8) * 208;
            if (wn == 0) {
#pragma unroll
                for (int j = 0; j < 7; j++) {
                    int c0 = base_col + j * 8 + 2 * l4;
                    *(float2*)&d_Zp[b0 + c0] = make_float2(acc[mt][j][0], acc[mt][j][1]);
                    *(float2*)&d_Zp[b1 + c0] = make_float2(acc[mt][j][2], acc[mt][j][3]);
                }
            } else {
#pragma unroll
                for (int j = 0; j < 5; j++) {
                    int c0 = base_col + 56 + j * 8 + 2 * l4;
                    *(float2*)&d_Zp[b0 + c0] = make_float2(acc[mt][j][0], acc[mt][j][1]);
                    *(float2*)&d_Zp[b1 + c0] = make_float2(acc[mt][j][2], acc[mt][j][3]);
                }
                if (h == 0) {
                    int c0 = 96 + 2 * l4;
                    *(float2*)&d_Zp[b0 + c0] = make_float2(acc[mt][5][0], acc[mt][5][1]);
                    *(float2*)&d_Zp[b1 + c0] = make_float2(acc[mt][5][2], acc[mt][5][3]);
                }
            }
        }
#pragma unroll
        for (int a = 0; a < 2; a++)
#pragma unroll
            for (int b = 0; b < 7; b++)
#pragma unroll
                for (int q = 0; q < 4; q++) acc[a][b][q] = 0.f;
    };

    load_tiles(m);
    __syncthreads();
    load_stage(0, 0); load_stage(1, 1);

    __half2 pb[4];
    const int s_cb = (2 * l4) * 2;       // byte offset of j0 within S row

    for (int t = 0; t < T; t++) {
        int u = u0 + (t >> 1);
        int mblk = u >> 7;
        if (mblk != m) {
            flush(m);
            __syncthreads();
            load_tiles(mblk);
            __syncthreads();
            m = mblk;
        }
        asm volatile("cp.async.wait_group 1;\n" ::: "memory");
        __syncthreads();
        if (t + 2 < T) load_stage((t + 2) % NSTB, t + 2);
        else asm volatile("cp.async.commit_group;\n");

        if ((t & 1) == 0) {
            int iu = u & 127;
#pragma unroll
            for (int t4 = 0; t4 < 4; t4++) {
                __half ph = *(const __half*)(smem + SM_P + (m_base + gq + 8 * t4) * 264 + iu * 2);
                pb[t4] = __half2half2(ph);
            }
        }
        const char* bst = smem + SM_B + (t % NSTB) * BSTG;

#pragma unroll
        for (int ss = 0; ss < 4; ss++) {
            int jb = (t & 1) * 64 + ss * 16;
            // A fragments (K-only -> same for both N-halves)
            uint32_t afr[2][4];
#pragma unroll
            for (int mt = 0; mt < 2; mt++) {
                const char* r0p = smem + SM_S + (m_base + mt * 16 + gq) * 272 + jb * 2 + s_cb;
                const char* r1p = r0p + 8 * 272;
                __half2 s00 = *(const __half2*)(r0p);
                __half2 s10 = *(const __half2*)(r1p);
                __half2 s01 = *(const __half2*)(r0p + 16);
                __half2 s11 = *(const __half2*)(r1p + 16);
                __half2 a0 = __hmul2(pb[mt * 2],     s00);
                __half2 a1 = __hmul2(pb[mt * 2 + 1], s10);
                __half2 a2 = __hmul2(pb[mt * 2],     s01);
                __half2 a3 = __hmul2(pb[mt * 2 + 1], s11);
                afr[mt][0] = *(uint32_t*)&a0; afr[mt][1] = *(uint32_t*)&a1;
                afr[mt][2] = *(uint32_t*)&a2; afr[mt][3] = *(uint32_t*)&a3;
            }

#define MMA_TILE(jj, tl)                                                        \
            {                                                                   \
                const char* brow = bst + ((tl) * 8 + gq) * BROW + ss * 32 + l4 * 4; \
                uint32_t b0 = *(const uint32_t*)(brow);                         \
                uint32_t b1 = *(const uint32_t*)(brow + 16);                    \
                _Pragma("unroll")                                               \
                for (int mt = 0; mt < 2; mt++) {                                \
                    asm volatile(                                               \
                        "mma.sync.aligned.m16n8k16.row.col.f32.f16.f16.f32 "    \
                        "{%0,%1,%2,%3}, {%4,%5,%6,%7}, {%8,%9}, {%0,%1,%2,%3};" \
                        : "+f"(acc[mt][jj][0]), "+f"(acc[mt][jj][1]),           \
                          "+f"(acc[mt][jj][2]), "+f"(acc[mt][jj][3])            \
                        : "r"(afr[mt][0]), "r"(afr[mt][1]),                     \
                          "r"(afr[mt][2]), "r"(afr[mt][3]),                     \
                          "r"(b0), "r"(b1));                                    \
                }                                                               \
            }

            if (wn == 0) {
#pragma unroll
                for (int j = 0; j < 7; j++) MMA_TILE(j, j)
            } else {
#pragma unroll
                for (int j = 0; j < 5; j++) MMA_TILE(j, 7 + j)
                if (h == 0) MMA_TILE(5, 12)
            }
#undef MMA_TILE
        }
    }

    flush(m);
}

// ---------------- epilogue: sum 4 partial slots, bias+relu, @W2 ----------------
__global__ void k_final(const float* __restrict__ b1, const float* __restrict__ W2,
                        const float* __restrict__ b2, float* __restrict__ out) {
    int g = (blockIdx.x * blockDim.x + threadIdx.x) >> 5;
    int lane = threadIdx.x & 31;
    if (g >= GG) return;
    float a0 = 0.f, a1 = 0.f;
    for (int n = lane; n < NOUT; n += 32) {
        float v = b1[n];
#pragma unroll
        for (int zz = 0; zz < NSLOTS_ZP; zz++) v += d_Zp[((size_t)zz * GG + g) * 208 + n];
        v = fmaxf(v, 0.f);
        a0 += v * W2[n * 2];
        a1 += v * W2[n * 2 + 1];
    }
#pragma unroll
    for (int o = 16; o; o >>= 1) {
        a0 += __shfl_down_sync(0xffffffffu, a0, o);
        a1 += __shfl_down_sync(0xffffffffu, a1, o);
    }
    if (lane == 0) { out[g * 2] = a0 + b2[0]; out[g * 2 + 1] = a1 + b2[1]; }
}

// ---------------- host ----------------
extern "C" void kernel_launch(void* const* d_in, const int* in_sizes, int n_in,
                              void* d_out, int out_size) {
    const float* x       = (const float*)d_in[0];
    const int*   ei      = (const int*)d_in[1];
    const int*   set_idx = (const int*)d_in[2];
    const float* ir      = (const float*)d_in[4];
    const float* Wl      = (const float*)d_in[5];
    const float* bl      = (const float*)d_in[6];
    const float* Wr      = (const float*)d_in[7];
    const float* Wir     = (const float*)d_in[8];
    const float* bir     = (const float*)d_in[9];
    const float* W1      = (const float*)d_in[10];
    const float* b1      = (const float*)d_in[11];
    const float* W2      = (const float*)d_in[12];
    const float* b2      = (const float*)d_in[13];
    float* out = (float*)d_out;

    // one-time host-side setup (streams/events are host resources, no dev mem)
    static cudaStream_t s1 = nullptr, s2 = nullptr;
    static cudaEvent_t ef = nullptr, e1 = nullptr, e2 = nullptr;
    static int nsm = 0;
    if (!s1) {
        cudaStreamCreateWithFlags(&s1, cudaStreamNonBlocking);
        cudaStreamCreateWithFlags(&s2, cudaStreamNonBlocking);
        cudaEventCreateWithFlags(&ef, cudaEventDisableTiming);
        cudaEventCreateWithFlags(&e1, cudaEventDisableTiming);
        cudaEventCreateWithFlags(&e2, cudaEventDisableTiming);
        cudaFuncSetAttribute(k_decode, cudaFuncAttributeMaxDynamicSharedMemorySize, SM_TOTAL);
        cudaDeviceGetAttribute(&nsm, cudaDevAttrMultiProcessorCount, 0);
        if (nsm < 4) nsm = 4;
    }

    void *p_mark, *p_cnt, *p_zp, *p_bits;
    cudaGetSymbolAddress(&p_mark, d_mark);
    cudaGetSymbolAddress(&p_cnt,  d_cnt);
    cudaGetSymbolAddress(&p_zp,   d_Zp);
    cudaGetSymbolAddress(&p_bits, d_bits);
    cudaMemsetAsync(p_mark, 0xFF, (size_t)NN * 4, 0);
    cudaMemsetAsync(p_bits, 0,    (size_t)(NN / 32) * 4, 0);
    cudaMemsetAsync(p_cnt,  0,    (size_t)NSLOT * 4, 0);

    // fork: independent stages on side streams
    cudaEventRecord(ef, 0);
    cudaStreamWaitEvent(s1, ef, 0);
    cudaStreamWaitEvent(s2, ef, 0);
    cudaMemsetAsync(p_zp, 0, (size_t)NSLOTS_ZP * GG * 208 * 4, s1);
    k_prep<<<dim3(512, 7), dim3(32, 8), 0, s1>>>(W1);
    k_sgemm<<<GG / 64, 256, 0, s2>>>(ir, Wir, bir);

    // main chain on origin stream
    k_mark<<<NSLOT / 256, 256>>>(set_idx);
    k_fill<<<EE / 2048, 256>>>(ei);
    k_agg<<<NSLOT / 8, 256>>>(x);
    k_hgemm<<<NSLOT / 128, 256>>>(Wl, Wr, bl);

    // join
    cudaEventRecord(e1, s1);
    cudaEventRecord(e2, s2);
    cudaStreamWaitEvent(0, e1, 0);
    cudaStreamWaitEvent(0, e2, 0);

    k_decode<<<2 * nsm, 256, SM_TOTAL>>>();
    k_final<<<(GG * 32 + 255) / 256, 256>>>(b1, W2, b2, out);
}